// round 1
// baseline (speedup 1.0000x reference)
#include <cuda_runtime.h>
#include <math.h>

// GraphSAGE encoder: 2x SAGEConv(mean) + ReLU, linear head, log_softmax.
// Shapes: N=100000 nodes, E=1600000 edges, D=64 throughout.

#define MAXN 100000
#define MAXE 1600000
#define D 64

// Scratch (device globals: no allocation allowed in kernel_launch)
__device__ float g_agg[MAXN * D];
__device__ float g_deg[MAXN];
__device__ float g_h1[MAXN * D];
__device__ float g_h2[MAXN * D];
__device__ int   g_idx64;   // 1 if edge_index is int64, 0 if int32

// ---------------------------------------------------------------------------
// Detect edge_index dtype: if the data is little-endian int64 with values in
// [0, N), every high 32-bit word is zero. If it is int32, odd positions are
// independent random values in [0, N) -> P(8 zeros) ~ 1e-40.
// ---------------------------------------------------------------------------
__global__ void detect_kernel(const int* __restrict__ ei32) {
    int allz = 1;
#pragma unroll
    for (int i = 0; i < 8; i++) allz &= (ei32[2 * i + 1] == 0);
    g_idx64 = allz;
}

__global__ void zero_kernel(float* __restrict__ p, long long n) {
    long long i = (long long)blockIdx.x * blockDim.x + threadIdx.x;
    long long stride = (long long)gridDim.x * blockDim.x;
    for (; i < n; i += stride) p[i] = 0.0f;
}

// ---------------------------------------------------------------------------
// Edge aggregation: 16 threads per edge, each handles one float4 of the
// 64-float feature row. Gather feat[src] (L2-resident), reduce-add into
// agg[dst] with red.global.add.v4.f32 (one REDG.128 per thread per edge).
// ---------------------------------------------------------------------------
__global__ void agg_kernel(const float* __restrict__ feat,
                           const void* __restrict__ ei,
                           float* __restrict__ agg,
                           float* __restrict__ deg,
                           int E, int do_deg) {
    const int is64 = g_idx64;
    long long gid = (long long)blockIdx.x * blockDim.x + threadIdx.x;
    long long e = gid >> 4;
    int q = (int)(gid & 15);
    if (e >= E) return;

    long long s, d;
    if (is64) {
        const long long* p = (const long long*)ei;
        s = p[e];
        d = p[(long long)E + e];
    } else {
        const int* p = (const int*)ei;
        s = p[e];
        d = p[(long long)E + e];
    }

    float4 v = *(const float4*)(feat + s * D + q * 4);
    float* dp = agg + d * D + q * 4;
    asm volatile("red.global.add.v4.f32 [%0], {%1,%2,%3,%4};"
                 :: "l"(dp), "f"(v.x), "f"(v.y), "f"(v.z), "f"(v.w)
                 : "memory");
    if (do_deg && q == 0) atomicAdd(&deg[d], 1.0f);
}

// ---------------------------------------------------------------------------
// SAGE node update: h[n] = relu( (agg[n]/max(deg,1)) @ Wl^T + bl + x[n] @ Wr^T )
// Block = 256 threads, 16 nodes/tile, 4 output features per thread.
// Weights transposed in SMEM (float4 conflict-free reads).
// ---------------------------------------------------------------------------
__global__ void sage_kernel(const float* __restrict__ xin,
                            const float* __restrict__ agg,
                            const float* __restrict__ deg,
                            const float* __restrict__ Wl,
                            const float* __restrict__ bl,
                            const float* __restrict__ Wr,
                            float* __restrict__ hout, int N) {
    __shared__ __align__(16) float Wlt[D * D];
    __shared__ __align__(16) float Wrt[D * D];
    __shared__ float bls[D];
    __shared__ float mean_sh[16][D + 1];
    __shared__ float x_sh[16][D + 1];

    const int tid = threadIdx.x;
    for (int i = tid; i < D * D; i += 256) {
        int j = i / D, k = i % D;
        Wlt[k * D + j] = Wl[i];
        Wrt[k * D + j] = Wr[i];
    }
    if (tid < D) bls[tid] = bl[tid];

    const int ntiles = (N + 15) / 16;
    const int i_node = tid >> 4;       // node within tile
    const int j0 = (tid & 15) * 4;     // output feature quad

    for (int tile = blockIdx.x; tile < ntiles; tile += gridDim.x) {
        const int base = tile * 16;
        __syncthreads();               // protect shared reuse across iterations
        for (int idx = tid; idx < 16 * D; idx += 256) {
            int i = idx / D, k = idx % D;
            int n = base + i;
            if (n < N) {
                float r = 1.0f / fmaxf(deg[n], 1.0f);
                mean_sh[i][k] = agg[(long long)n * D + k] * r;
                x_sh[i][k]    = xin[(long long)n * D + k];
            }
        }
        __syncthreads();

        float4 acc = make_float4(0.f, 0.f, 0.f, 0.f);
#pragma unroll
        for (int k = 0; k < D; k++) {
            float m  = mean_sh[i_node][k];
            float xv = x_sh[i_node][k];
            float4 wl = *(const float4*)&Wlt[k * D + j0];
            float4 wr = *(const float4*)&Wrt[k * D + j0];
            acc.x += m * wl.x + xv * wr.x;
            acc.y += m * wl.y + xv * wr.y;
            acc.z += m * wl.z + xv * wr.z;
            acc.w += m * wl.w + xv * wr.w;
        }
        int n = base + i_node;
        if (n < N) {
            acc.x = fmaxf(acc.x + bls[j0 + 0], 0.0f);
            acc.y = fmaxf(acc.y + bls[j0 + 1], 0.0f);
            acc.z = fmaxf(acc.z + bls[j0 + 2], 0.0f);
            acc.w = fmaxf(acc.w + bls[j0 + 3], 0.0f);
            *(float4*)&hout[(long long)n * D + j0] = acc;
        }
    }
}

// ---------------------------------------------------------------------------
// Output head: logits = h @ Wout^T + bout, then row-wise log_softmax.
// One warp per node; each lane owns logits (lane, lane+32).
// ---------------------------------------------------------------------------
__global__ void out_kernel(const float* __restrict__ h,
                           const float* __restrict__ Wout,
                           const float* __restrict__ bout,
                           float* __restrict__ out, int N) {
    __shared__ float Wt[D * D];
    __shared__ float bs[D];
    __shared__ float row[8][D];

    const int tid = threadIdx.x;
    for (int i = tid; i < D * D; i += 256) {
        int j = i / D, k = i % D;
        Wt[k * D + j] = Wout[i];
    }
    if (tid < D) bs[tid] = bout[tid];
    __syncthreads();

    const int w = tid >> 5, lane = tid & 31;
    const int ngroups = (N + 7) / 8;

    for (int g = blockIdx.x; g < ngroups; g += gridDim.x) {
        int n = g * 8 + w;
        if (n < N) {
            row[w][lane]      = h[(long long)n * D + lane];
            row[w][32 + lane] = h[(long long)n * D + 32 + lane];
            __syncwarp();
            float l0 = 0.f, l1 = 0.f;
#pragma unroll
            for (int k = 0; k < D; k++) {
                float r = row[w][k];
                l0 += r * Wt[k * D + lane];
                l1 += r * Wt[k * D + 32 + lane];
            }
            l0 += bs[lane];
            l1 += bs[32 + lane];
            float m = fmaxf(l0, l1);
#pragma unroll
            for (int o = 16; o; o >>= 1)
                m = fmaxf(m, __shfl_xor_sync(0xffffffff, m, o));
            float s = expf(l0 - m) + expf(l1 - m);
#pragma unroll
            for (int o = 16; o; o >>= 1)
                s += __shfl_xor_sync(0xffffffff, s, o);
            float lse = m + logf(s);
            out[(long long)n * D + lane]      = l0 - lse;
            out[(long long)n * D + 32 + lane] = l1 - lse;
            __syncwarp();   // row[w] reused next group iteration
        }
    }
}

// ---------------------------------------------------------------------------
extern "C" void kernel_launch(void* const* d_in, const int* in_sizes, int n_in,
                              void* d_out, int out_size) {
    const float* x    = (const float*)d_in[0];
    const void*  ei   = d_in[1];                 // int64 or int32, detected
    const float* W1l  = (const float*)d_in[2];
    const float* b1l  = (const float*)d_in[3];
    const float* W1r  = (const float*)d_in[4];
    const float* W2l  = (const float*)d_in[5];
    const float* b2l  = (const float*)d_in[6];
    const float* W2r  = (const float*)d_in[7];
    const float* Wout = (const float*)d_in[8];
    const float* bout = (const float*)d_in[9];

    const int N = in_sizes[0] / D;
    const int E = in_sizes[1] / 2;

    float* agg; cudaGetSymbolAddress((void**)&agg, g_agg);
    float* deg; cudaGetSymbolAddress((void**)&deg, g_deg);
    float* h1;  cudaGetSymbolAddress((void**)&h1,  g_h1);
    float* h2;  cudaGetSymbolAddress((void**)&h2,  g_h2);

    detect_kernel<<<1, 1>>>((const int*)ei);

    const long long aggN = (long long)N * D;
    zero_kernel<<<1024, 256>>>(agg, aggN);
    zero_kernel<<<256, 256>>>(deg, N);

    const int eblocks = (int)(((long long)E * 16 + 255) / 256);

    // Layer 1
    agg_kernel<<<eblocks, 256>>>(x, ei, agg, deg, E, 1);
    sage_kernel<<<592, 256>>>(x, agg, deg, W1l, b1l, W1r, h1, N);

    // Layer 2
    zero_kernel<<<1024, 256>>>(agg, aggN);
    agg_kernel<<<eblocks, 256>>>(h1, ei, agg, deg, E, 0);
    sage_kernel<<<592, 256>>>(h1, agg, deg, W2l, b2l, W2r, h2, N);

    // Head + log_softmax
    out_kernel<<<1184, 256>>>(h2, Wout, bout, (float*)d_out, N);
}

// round 2
// speedup vs baseline: 1.1757x; 1.1757x over previous
#include <cuda_runtime.h>
#include <math.h>

// GraphSAGE encoder: CSR-based (atomic-free) aggregation fused with the
// SAGE transform; layer 2 additionally fused with the output head + log_softmax.
// N=100000 nodes, E=1600000 edges, D=64 everywhere.

#define MAXN 100000
#define MAXE 1600000
#define D 64

// Device-global scratch (no allocation allowed)
__device__ int   g_cnt[MAXN];          // per-node in-degree (histogram)
__device__ int   g_ptr[MAXN + 1];      // CSR row offsets
__device__ int   g_cur[MAXN];          // scatter cursors
__device__ int   g_bsum[256];          // scan block sums
__device__ int   g_boff[256];          // scan block offsets
__device__ int   g_csr[MAXE];          // CSR column (src) indices
__device__ float g_h1[MAXN * D];       // layer-1 activations
__device__ int   g_idx64;              // 1 if edge_index is int64

// ---------------------------------------------------------------------------
// Detect edge_index dtype: int64 little-endian values < N have zero high words.
// ---------------------------------------------------------------------------
__global__ void detect_kernel(const int* __restrict__ ei32) {
    int allz = 1;
#pragma unroll
    for (int i = 0; i < 8; i++) allz &= (ei32[2 * i + 1] == 0);
    g_idx64 = allz;
}

__global__ void zero_int_kernel(int* __restrict__ p, int n) {
    int i = blockIdx.x * blockDim.x + threadIdx.x;
    int stride = gridDim.x * blockDim.x;
    for (; i < n; i += stride) p[i] = 0;
}

// ---------------------------------------------------------------------------
// CSR build
// ---------------------------------------------------------------------------
__global__ void hist_kernel(const void* __restrict__ ei, int* __restrict__ cnt, int E) {
    const int is64 = g_idx64;
    int e = blockIdx.x * blockDim.x + threadIdx.x;
    if (e >= E) return;
    int d;
    if (is64) d = (int)((const long long*)ei)[(long long)E + e];
    else      d = ((const int*)ei)[(long long)E + e];
    atomicAdd(&cnt[d], 1);
}

// pass1: per-1024-element block exclusive scan (partial), block totals to bsum
__global__ void scan_pass1(const int* __restrict__ cnt, int* __restrict__ ptr,
                           int* __restrict__ bsum, int N) {
    __shared__ int ssum[256];
    const int tid = threadIdx.x;
    const int base = blockIdx.x * 1024 + tid * 4;
    int v0 = (base + 0 < N) ? cnt[base + 0] : 0;
    int v1 = (base + 1 < N) ? cnt[base + 1] : 0;
    int v2 = (base + 2 < N) ? cnt[base + 2] : 0;
    int v3 = (base + 3 < N) ? cnt[base + 3] : 0;
    int s = v0 + v1 + v2 + v3;
    ssum[tid] = s;
    __syncthreads();
    // Hillis-Steele inclusive scan over 256 thread sums
    for (int st = 1; st < 256; st <<= 1) {
        int t = (tid >= st) ? ssum[tid - st] : 0;
        __syncthreads();
        ssum[tid] += t;
        __syncthreads();
    }
    int off = ssum[tid] - s;   // exclusive prefix for this thread
    if (base + 0 < N) ptr[base + 0] = off;            off += v0;
    if (base + 1 < N) ptr[base + 1] = off;            off += v1;
    if (base + 2 < N) ptr[base + 2] = off;            off += v2;
    if (base + 3 < N) ptr[base + 3] = off;
    if (tid == 255) bsum[blockIdx.x] = ssum[255];
}

__global__ void scan_pass2(const int* __restrict__ bsum, int* __restrict__ boff,
                           int nb, int* __restrict__ ptr, int N) {
    int run = 0;
    for (int b = 0; b < nb; b++) { boff[b] = run; run += bsum[b]; }
    ptr[N] = run;
}

__global__ void scan_pass3(int* __restrict__ ptr, const int* __restrict__ boff,
                           int* __restrict__ cur, int N) {
    int i = blockIdx.x * 1024 + threadIdx.x;
    if (i < N) {
        int v = ptr[i] + boff[blockIdx.x];
        ptr[i] = v;
        cur[i] = v;
    }
}

__global__ void scatter_kernel(const void* __restrict__ ei, int* __restrict__ cur,
                               int* __restrict__ csr, int E) {
    const int is64 = g_idx64;
    int e = blockIdx.x * blockDim.x + threadIdx.x;
    if (e >= E) return;
    int s, d;
    if (is64) {
        const long long* p = (const long long*)ei;
        s = (int)p[e];
        d = (int)p[(long long)E + e];
    } else {
        const int* p = (const int*)ei;
        s = p[e];
        d = p[(long long)E + e];
    }
    int pos = atomicAdd(&cur[d], 1);
    csr[pos] = s;
}

// ---------------------------------------------------------------------------
// Fused SAGE layer: CSR gather (mean) + dual matmul + bias + ReLU.
// HEAD variant additionally applies the output head + log_softmax.
// Block: 256 threads = 16 groups of 16; each group owns 2 nodes (tile = 32).
// Each group lane q owns feature quad [4q, 4q+4).
// ---------------------------------------------------------------------------
template<bool HEAD>
__global__ void __launch_bounds__(256) fused_sage(
    const float* __restrict__ feat,
    const int*   __restrict__ ptr,
    const int*   __restrict__ csr,
    const float* __restrict__ Wl, const float* __restrict__ bl,
    const float* __restrict__ Wr,
    const float* __restrict__ Wo, const float* __restrict__ bo,
    float* __restrict__ out, int N)
{
    __shared__ __align__(16) float Wlt[D * D];
    __shared__ __align__(16) float Wrt[D * D];
    __shared__ float bls[D];
    __shared__ __align__(16) float Wot[HEAD ? D * D : 1];
    __shared__ float bos[HEAD ? D : 1];
    __shared__ float msh[32][D + 1];
    __shared__ float xsh[32][D + 1];

    const int tid = threadIdx.x;
    for (int i = tid; i < D * D; i += 256) {
        int r = i >> 6, c = i & 63;
        Wlt[c * D + r] = Wl[i];
        Wrt[c * D + r] = Wr[i];
        if (HEAD) Wot[c * D + r] = Wo[i];
    }
    if (tid < D) { bls[tid] = bl[tid]; if (HEAD) bos[tid] = bo[tid]; }

    const int g = tid >> 4;                         // group 0..15
    const int q = tid & 15;                         // lane in group
    const int j0 = q * 4;                           // feature quad base
    const unsigned gmask = ((tid & 31) < 16) ? 0x0000FFFFu : 0xFFFF0000u;
    const int ntiles = (N + 31) / 32;

    for (int tile = blockIdx.x; tile < ntiles; tile += gridDim.x) {
        const int base = tile * 32;
        __syncthreads();                            // protect smem reuse

        // ---- gather + mean for this group's 2 nodes ----
#pragma unroll
        for (int v = 0; v < 2; v++) {
            const int row = 2 * g + v;
            const int n = base + row;
            float4 acc = make_float4(0.f, 0.f, 0.f, 0.f);
            int rs = 0, re = 0;
            if (n < N) { rs = ptr[n]; re = ptr[n + 1]; }
            for (int b = rs; b < re; b += 16) {
                int idx = 0;
                if (b + q < re) idx = csr[b + q];
                const int cnt = min(16, re - b);
                int j = 0;
                for (; j + 4 <= cnt; j += 4) {
                    int s0 = __shfl_sync(gmask, idx, j + 0, 16);
                    int s1 = __shfl_sync(gmask, idx, j + 1, 16);
                    int s2 = __shfl_sync(gmask, idx, j + 2, 16);
                    int s3 = __shfl_sync(gmask, idx, j + 3, 16);
                    float4 a = *(const float4*)(feat + (size_t)s0 * D + j0);
                    float4 b4 = *(const float4*)(feat + (size_t)s1 * D + j0);
                    float4 c = *(const float4*)(feat + (size_t)s2 * D + j0);
                    float4 d4 = *(const float4*)(feat + (size_t)s3 * D + j0);
                    acc.x += a.x + b4.x + c.x + d4.x;
                    acc.y += a.y + b4.y + c.y + d4.y;
                    acc.z += a.z + b4.z + c.z + d4.z;
                    acc.w += a.w + b4.w + c.w + d4.w;
                }
                for (; j < cnt; j++) {
                    int s0 = __shfl_sync(gmask, idx, j, 16);
                    float4 a = *(const float4*)(feat + (size_t)s0 * D + j0);
                    acc.x += a.x; acc.y += a.y; acc.z += a.z; acc.w += a.w;
                }
            }
            const float invd = 1.0f / fmaxf((float)(re - rs), 1.0f);
            msh[row][j0 + 0] = acc.x * invd;
            msh[row][j0 + 1] = acc.y * invd;
            msh[row][j0 + 2] = acc.z * invd;
            msh[row][j0 + 3] = acc.w * invd;
            if (n < N) {
                float4 xv = *(const float4*)(feat + (size_t)n * D + j0);
                xsh[row][j0 + 0] = xv.x;
                xsh[row][j0 + 1] = xv.y;
                xsh[row][j0 + 2] = xv.z;
                xsh[row][j0 + 3] = xv.w;
            } else {
                xsh[row][j0 + 0] = 0.f; xsh[row][j0 + 1] = 0.f;
                xsh[row][j0 + 2] = 0.f; xsh[row][j0 + 3] = 0.f;
            }
        }
        __syncthreads();

        // ---- dual matmul for 2 nodes (W LDS amortized over both) ----
        float4 a0 = make_float4(0.f, 0.f, 0.f, 0.f);
        float4 a1 = make_float4(0.f, 0.f, 0.f, 0.f);
        const float* m0 = msh[2 * g];
        const float* m1 = msh[2 * g + 1];
        const float* x0 = xsh[2 * g];
        const float* x1 = xsh[2 * g + 1];
#pragma unroll
        for (int k = 0; k < D; k++) {
            float4 wl = *(const float4*)&Wlt[k * D + j0];
            float4 wr = *(const float4*)&Wrt[k * D + j0];
            float mm0 = m0[k], xx0 = x0[k];
            float mm1 = m1[k], xx1 = x1[k];
            a0.x += mm0 * wl.x + xx0 * wr.x;
            a0.y += mm0 * wl.y + xx0 * wr.y;
            a0.z += mm0 * wl.z + xx0 * wr.z;
            a0.w += mm0 * wl.w + xx0 * wr.w;
            a1.x += mm1 * wl.x + xx1 * wr.x;
            a1.y += mm1 * wl.y + xx1 * wr.y;
            a1.z += mm1 * wl.z + xx1 * wr.z;
            a1.w += mm1 * wl.w + xx1 * wr.w;
        }
        a0.x = fmaxf(a0.x + bls[j0 + 0], 0.f);
        a0.y = fmaxf(a0.y + bls[j0 + 1], 0.f);
        a0.z = fmaxf(a0.z + bls[j0 + 2], 0.f);
        a0.w = fmaxf(a0.w + bls[j0 + 3], 0.f);
        a1.x = fmaxf(a1.x + bls[j0 + 0], 0.f);
        a1.y = fmaxf(a1.y + bls[j0 + 1], 0.f);
        a1.z = fmaxf(a1.z + bls[j0 + 2], 0.f);
        a1.w = fmaxf(a1.w + bls[j0 + 3], 0.f);

        const int n0 = base + 2 * g, n1 = n0 + 1;

        if (!HEAD) {
            if (n0 < N) *(float4*)&out[(size_t)n0 * D + j0] = a0;
            if (n1 < N) *(float4*)&out[(size_t)n1 * D + j0] = a1;
        } else {
            // stage h into msh (all msh/xsh readers are done after this sync)
            __syncthreads();
            msh[2 * g][j0 + 0] = a0.x; msh[2 * g][j0 + 1] = a0.y;
            msh[2 * g][j0 + 2] = a0.z; msh[2 * g][j0 + 3] = a0.w;
            msh[2 * g + 1][j0 + 0] = a1.x; msh[2 * g + 1][j0 + 1] = a1.y;
            msh[2 * g + 1][j0 + 2] = a1.z; msh[2 * g + 1][j0 + 3] = a1.w;
            __syncthreads();

            float4 l0 = make_float4(bos[j0], bos[j0 + 1], bos[j0 + 2], bos[j0 + 3]);
            float4 l1 = l0;
            const float* h0 = msh[2 * g];
            const float* h1p = msh[2 * g + 1];
#pragma unroll
            for (int k = 0; k < D; k++) {
                float4 wo = *(const float4*)&Wot[k * D + j0];
                float hh0 = h0[k], hh1 = h1p[k];
                l0.x += hh0 * wo.x; l0.y += hh0 * wo.y;
                l0.z += hh0 * wo.z; l0.w += hh0 * wo.w;
                l1.x += hh1 * wo.x; l1.y += hh1 * wo.y;
                l1.z += hh1 * wo.z; l1.w += hh1 * wo.w;
            }
            // log_softmax over the group's 64 logits (4 per lane x 16 lanes)
            float mx0 = fmaxf(fmaxf(l0.x, l0.y), fmaxf(l0.z, l0.w));
            float mx1 = fmaxf(fmaxf(l1.x, l1.y), fmaxf(l1.z, l1.w));
#pragma unroll
            for (int o = 8; o; o >>= 1) {
                mx0 = fmaxf(mx0, __shfl_xor_sync(gmask, mx0, o, 16));
                mx1 = fmaxf(mx1, __shfl_xor_sync(gmask, mx1, o, 16));
            }
            float sm0 = expf(l0.x - mx0) + expf(l0.y - mx0) +
                        expf(l0.z - mx0) + expf(l0.w - mx0);
            float sm1 = expf(l1.x - mx1) + expf(l1.y - mx1) +
                        expf(l1.z - mx1) + expf(l1.w - mx1);
#pragma unroll
            for (int o = 8; o; o >>= 1) {
                sm0 += __shfl_xor_sync(gmask, sm0, o, 16);
                sm1 += __shfl_xor_sync(gmask, sm1, o, 16);
            }
            float lse0 = mx0 + logf(sm0);
            float lse1 = mx1 + logf(sm1);
            if (n0 < N) {
                float4 r = make_float4(l0.x - lse0, l0.y - lse0, l0.z - lse0, l0.w - lse0);
                *(float4*)&out[(size_t)n0 * D + j0] = r;
            }
            if (n1 < N) {
                float4 r = make_float4(l1.x - lse1, l1.y - lse1, l1.z - lse1, l1.w - lse1);
                *(float4*)&out[(size_t)n1 * D + j0] = r;
            }
        }
    }
}

// ---------------------------------------------------------------------------
extern "C" void kernel_launch(void* const* d_in, const int* in_sizes, int n_in,
                              void* d_out, int out_size) {
    const float* x    = (const float*)d_in[0];
    const void*  ei   = d_in[1];
    const float* W1l  = (const float*)d_in[2];
    const float* b1l  = (const float*)d_in[3];
    const float* W1r  = (const float*)d_in[4];
    const float* W2l  = (const float*)d_in[5];
    const float* b2l  = (const float*)d_in[6];
    const float* W2r  = (const float*)d_in[7];
    const float* Wout = (const float*)d_in[8];
    const float* bout = (const float*)d_in[9];

    const int N = in_sizes[0] / D;
    const int E = in_sizes[1] / 2;

    int*   cnt;  cudaGetSymbolAddress((void**)&cnt,  g_cnt);
    int*   ptr;  cudaGetSymbolAddress((void**)&ptr,  g_ptr);
    int*   cur;  cudaGetSymbolAddress((void**)&cur,  g_cur);
    int*   bsum; cudaGetSymbolAddress((void**)&bsum, g_bsum);
    int*   boff; cudaGetSymbolAddress((void**)&boff, g_boff);
    int*   csr;  cudaGetSymbolAddress((void**)&csr,  g_csr);
    float* h1;   cudaGetSymbolAddress((void**)&h1,   g_h1);

    detect_kernel<<<1, 1>>>((const int*)ei);

    // CSR build
    zero_int_kernel<<<128, 256>>>(cnt, N);
    const int eblocks = (E + 255) / 256;
    hist_kernel<<<eblocks, 256>>>(ei, cnt, E);
    const int nb = (N + 1023) / 1024;
    scan_pass1<<<nb, 256>>>(cnt, ptr, bsum, N);
    scan_pass2<<<1, 1>>>(bsum, boff, nb, ptr, N);
    scan_pass3<<<nb, 1024>>>(ptr, boff, cur, N);
    scatter_kernel<<<eblocks, 256>>>(ei, cur, csr, E);

    const int ntiles = (N + 31) / 32;

    // Layer 1 (fused gather + transform)
    fused_sage<false><<<ntiles, 256>>>(x, ptr, csr, W1l, b1l, W1r,
                                       nullptr, nullptr, h1, N);
    // Layer 2 + head + log_softmax
    fused_sage<true><<<ntiles, 256>>>(h1, ptr, csr, W2l, b2l, W2r,
                                      Wout, bout, (float*)d_out, N);
}

// round 3
// speedup vs baseline: 2.4874x; 2.1157x over previous
#include <cuda_runtime.h>
#include <math.h>

// GraphSAGE encoder, split-phase:
//   CSR build (5 launches) -> gather/mean kernel -> dense SAGE transform kernel
//   (layer 2 transform fuses output head + log_softmax).
// N=100000, E=1600000, D=64.

#define MAXN 100000
#define MAXE 1600000
#define D 64

__device__ int   g_cnt[MAXN];
__device__ int   g_ptr[MAXN + 1];
__device__ int   g_cur[MAXN];
__device__ int   g_bsum[256];
__device__ int   g_csr[MAXE];
__device__ float g_mean[MAXN * D];
__device__ float g_h1[MAXN * D];
__device__ int   g_idx64;

// ---------------- f32x2 packed math helpers (Blackwell) ----------------
__device__ __forceinline__ unsigned long long pk2(float a) {
    unsigned long long r;
    asm("mov.b64 %0, {%1, %1};" : "=l"(r) : "f"(a));
    return r;
}
__device__ __forceinline__ void fma2(unsigned long long& d,
                                     unsigned long long a, unsigned long long b) {
    asm("fma.rn.f32x2 %0, %1, %2, %0;" : "+l"(d) : "l"(a), "l"(b));
}
__device__ __forceinline__ void add2(unsigned long long& d, unsigned long long a) {
    asm("add.rn.f32x2 %0, %0, %1;" : "+l"(d) : "l"(a));
}
__device__ __forceinline__ float lo2(unsigned long long v) {
    return __uint_as_float((unsigned)(v & 0xffffffffull));
}
__device__ __forceinline__ float hi2(unsigned long long v) {
    return __uint_as_float((unsigned)(v >> 32));
}

// ---------------- CSR build ----------------
// [0] init: zero cnt, detect edge dtype, ptr[N]=E
__global__ void init_kernel(const int* __restrict__ ei32, int* __restrict__ cnt,
                            int* __restrict__ ptr, int N, int E) {
    int i = blockIdx.x * blockDim.x + threadIdx.x;
    if (i < N) cnt[i] = 0;
    if (i == 0) {
        int allz = 1;
#pragma unroll
        for (int t = 0; t < 8; t++) allz &= (ei32[2 * t + 1] == 0);
        g_idx64 = allz;
        ptr[N] = E;
    }
}

// [1] histogram of dst
__global__ void hist_kernel(const void* __restrict__ ei, int* __restrict__ cnt, int E) {
    const int is64 = g_idx64;
    int e = blockIdx.x * blockDim.x + threadIdx.x;
    if (e >= E) return;
    int d;
    if (is64) d = (int)((const long long*)ei)[(long long)E + e];
    else      d = ((const int*)ei)[(long long)E + e];
    atomicAdd(&cnt[d], 1);
}

// [2] per-1024 block exclusive scan; block totals -> bsum
__global__ void scan_pass1(const int* __restrict__ cnt, int* __restrict__ ptr,
                           int* __restrict__ bsum, int N) {
    __shared__ int ssum[256];
    const int tid = threadIdx.x;
    const int base = blockIdx.x * 1024 + tid * 4;
    int v0 = (base + 0 < N) ? cnt[base + 0] : 0;
    int v1 = (base + 1 < N) ? cnt[base + 1] : 0;
    int v2 = (base + 2 < N) ? cnt[base + 2] : 0;
    int v3 = (base + 3 < N) ? cnt[base + 3] : 0;
    int s = v0 + v1 + v2 + v3;
    ssum[tid] = s;
    __syncthreads();
    for (int st = 1; st < 256; st <<= 1) {
        int t = (tid >= st) ? ssum[tid - st] : 0;
        __syncthreads();
        ssum[tid] += t;
        __syncthreads();
    }
    int off = ssum[tid] - s;
    if (base + 0 < N) ptr[base + 0] = off;  off += v0;
    if (base + 1 < N) ptr[base + 1] = off;  off += v1;
    if (base + 2 < N) ptr[base + 2] = off;  off += v2;
    if (base + 3 < N) ptr[base + 3] = off;
    if (tid == 255) bsum[blockIdx.x] = ssum[255];
}

// [3] fixup: add cross-block offsets (each block sums bsum[0..b) itself)
__global__ void scan_fixup(int* __restrict__ ptr, const int* __restrict__ bsum,
                           int* __restrict__ cur, int N) {
    __shared__ int off_sh;
    if (threadIdx.x == 0) {
        int o = 0;
        for (int j = 0; j < blockIdx.x; j++) o += bsum[j];
        off_sh = o;
    }
    __syncthreads();
    int i = blockIdx.x * 1024 + threadIdx.x;
    if (i < N) {
        int v = ptr[i] + off_sh;
        ptr[i] = v;
        cur[i] = v;
    }
}

// [4] scatter src into CSR slots
__global__ void scatter_kernel(const void* __restrict__ ei, int* __restrict__ cur,
                               int* __restrict__ csr, int E) {
    const int is64 = g_idx64;
    int e = blockIdx.x * blockDim.x + threadIdx.x;
    if (e >= E) return;
    int s, d;
    if (is64) {
        const long long* p = (const long long*)ei;
        s = (int)p[e];
        d = (int)p[(long long)E + e];
    } else {
        const int* p = (const int*)ei;
        s = p[e];
        d = p[(long long)E + e];
    }
    int pos = atomicAdd(&cur[d], 1);
    csr[pos] = s;
}

// ---------------- gather + mean (lean, high-occupancy, MLP-deep) ----------------
// 16 lanes per node; lane q owns feature quad [4q,4q+4). Main path: 16-neighbor
// batches, 8 loads in flight; remainder: predicated 4-wide.
__global__ void __launch_bounds__(256) gather_mean(
    const float* __restrict__ feat, const int* __restrict__ ptr,
    const int* __restrict__ csr, float* __restrict__ mean, int N)
{
    const int gid = blockIdx.x * 256 + threadIdx.x;
    const int n = gid >> 4;
    const int q = gid & 15;
    const unsigned gmask = ((threadIdx.x & 31) < 16) ? 0x0000FFFFu : 0xFFFF0000u;

    int rs = 0, re = 0;
    if (n < N) { rs = ptr[n]; re = ptr[n + 1]; }

    unsigned long long a0 = 0, a1 = 0, a2 = 0, a3 = 0;
    const float* fq = feat + q * 4;

    int b = rs;
    for (; b + 16 <= re; b += 16) {
        int idx = csr[b + q];
#pragma unroll
        for (int h = 0; h < 16; h += 8) {
            int s0 = __shfl_sync(gmask, idx, h + 0, 16);
            int s1 = __shfl_sync(gmask, idx, h + 1, 16);
            int s2 = __shfl_sync(gmask, idx, h + 2, 16);
            int s3 = __shfl_sync(gmask, idx, h + 3, 16);
            int s4 = __shfl_sync(gmask, idx, h + 4, 16);
            int s5 = __shfl_sync(gmask, idx, h + 5, 16);
            int s6 = __shfl_sync(gmask, idx, h + 6, 16);
            int s7 = __shfl_sync(gmask, idx, h + 7, 16);
            ulonglong2 v0 = *(const ulonglong2*)(fq + (size_t)s0 * D);
            ulonglong2 v1 = *(const ulonglong2*)(fq + (size_t)s1 * D);
            ulonglong2 v2 = *(const ulonglong2*)(fq + (size_t)s2 * D);
            ulonglong2 v3 = *(const ulonglong2*)(fq + (size_t)s3 * D);
            ulonglong2 v4 = *(const ulonglong2*)(fq + (size_t)s4 * D);
            ulonglong2 v5 = *(const ulonglong2*)(fq + (size_t)s5 * D);
            ulonglong2 v6 = *(const ulonglong2*)(fq + (size_t)s6 * D);
            ulonglong2 v7 = *(const ulonglong2*)(fq + (size_t)s7 * D);
            add2(a0, v0.x); add2(a1, v0.y);
            add2(a2, v1.x); add2(a3, v1.y);
            add2(a0, v2.x); add2(a1, v2.y);
            add2(a2, v3.x); add2(a3, v3.y);
            add2(a0, v4.x); add2(a1, v4.y);
            add2(a2, v5.x); add2(a3, v5.y);
            add2(a0, v6.x); add2(a1, v6.y);
            add2(a2, v7.x); add2(a3, v7.y);
        }
    }
    const int cnt = re - b;
    if (cnt > 0) {
        int idx = (b + q < re) ? csr[b + q] : 0;
#pragma unroll
        for (int j = 0; j < 16; j += 4) {
            if (j < cnt) {
                int s0 = __shfl_sync(gmask, idx, j + 0, 16);
                int s1 = __shfl_sync(gmask, idx, j + 1, 16);
                int s2 = __shfl_sync(gmask, idx, j + 2, 16);
                int s3 = __shfl_sync(gmask, idx, j + 3, 16);
                ulonglong2 v0 = *(const ulonglong2*)(fq + (size_t)s0 * D);
                add2(a0, v0.x); add2(a1, v0.y);
                if (j + 1 < cnt) {
                    ulonglong2 v1 = *(const ulonglong2*)(fq + (size_t)s1 * D);
                    add2(a2, v1.x); add2(a3, v1.y);
                }
                if (j + 2 < cnt) {
                    ulonglong2 v2 = *(const ulonglong2*)(fq + (size_t)s2 * D);
                    add2(a0, v2.x); add2(a1, v2.y);
                }
                if (j + 3 < cnt) {
                    ulonglong2 v3 = *(const ulonglong2*)(fq + (size_t)s3 * D);
                    add2(a2, v3.x); add2(a3, v3.y);
                }
            }
        }
    }

    if (n < N) {
        add2(a0, a2);
        add2(a1, a3);
        const float invd = 1.0f / fmaxf((float)(re - rs), 1.0f);
        float4 r;
        r.x = lo2(a0) * invd; r.y = hi2(a0) * invd;
        r.z = lo2(a1) * invd; r.w = hi2(a1) * invd;
        *(float4*)(mean + (size_t)n * D + q * 4) = r;
    }
}

// ---------------- dense SAGE transform (G=4 nodes/group, FFMA2) ----------------
// h = relu(mean @ Wl^T + bl + x @ Wr^T); HEAD: out = log_softmax(h @ Wo^T + bo).
// Block 256 = 16 groups x 16 lanes; group owns 4 nodes; lane owns output quad.
template<bool HEAD>
__global__ void __launch_bounds__(256) sage_transform(
    const float* __restrict__ mean, const float* __restrict__ x,
    const float* __restrict__ Wl, const float* __restrict__ bl,
    const float* __restrict__ Wr,
    const float* __restrict__ Wo, const float* __restrict__ bo,
    float* __restrict__ out, int N)
{
    extern __shared__ float smf[];
    float* Wlt   = smf;                              // [64][64] transposed
    float* Wrt   = Wlt + D * D;
    float* Wot   = Wrt + D * D;                      // HEAD only
    float* stage = Wot + (HEAD ? D * D : 0);         // [64][64] mean, then h
    float* xst   = stage + 64 * D;                   // [64][64] x
    float* bls   = xst + 64 * D;
    float* bos   = bls + D;

    const int tid = threadIdx.x;
    // Transposed weight staging, conflict-free (lanes write distinct banks).
#pragma unroll
    for (int it = 0; it < 4; it++) {
        int i = tid + it * 256;          // 1024 quad slots
        int r = i & 63;
        int c0 = (i >> 6) * 4;
        float4 w = *(const float4*)&Wl[r * D + c0];
        Wlt[(c0 + 0) * D + r] = w.x; Wlt[(c0 + 1) * D + r] = w.y;
        Wlt[(c0 + 2) * D + r] = w.z; Wlt[(c0 + 3) * D + r] = w.w;
        w = *(const float4*)&Wr[r * D + c0];
        Wrt[(c0 + 0) * D + r] = w.x; Wrt[(c0 + 1) * D + r] = w.y;
        Wrt[(c0 + 2) * D + r] = w.z; Wrt[(c0 + 3) * D + r] = w.w;
        if (HEAD) {
            w = *(const float4*)&Wo[r * D + c0];
            Wot[(c0 + 0) * D + r] = w.x; Wot[(c0 + 1) * D + r] = w.y;
            Wot[(c0 + 2) * D + r] = w.z; Wot[(c0 + 3) * D + r] = w.w;
        }
    }
    if (tid < D) { bls[tid] = bl[tid]; if (HEAD) bos[tid] = bo[tid]; }

    const int g4 = (tid >> 4) * 4;       // first of this group's 4 node rows
    const int q = tid & 15;
    const int j0 = q * 4;
    const int ntiles = (N + 63) / 64;

    for (int tile = blockIdx.x; tile < ntiles; tile += gridDim.x) {
        const int base = tile * 64;
        __syncthreads();
        // stage mean / x (zero-fill past N)
#pragma unroll
        for (int it = 0; it < 4; it++) {
            int i = tid + it * 256;
            int row = i >> 4, qq = (i & 15) * 4;
            int nidx = base + row;
            float4 mv = make_float4(0.f, 0.f, 0.f, 0.f), xv = mv;
            if (nidx < N) {
                mv = *(const float4*)(mean + (size_t)nidx * D + qq);
                xv = *(const float4*)(x    + (size_t)nidx * D + qq);
            }
            *(float4*)&stage[row * D + qq] = mv;
            *(float4*)&xst[row * D + qq]   = xv;
        }
        __syncthreads();

        unsigned long long acc[4][2] = {};
        for (int k4 = 0; k4 < D; k4 += 4) {
            float mq[4][4], xq[4][4];
#pragma unroll
            for (int v = 0; v < 4; v++) {
                float4 t = *(const float4*)&stage[(g4 + v) * D + k4];
                mq[v][0] = t.x; mq[v][1] = t.y; mq[v][2] = t.z; mq[v][3] = t.w;
                t = *(const float4*)&xst[(g4 + v) * D + k4];
                xq[v][0] = t.x; xq[v][1] = t.y; xq[v][2] = t.z; xq[v][3] = t.w;
            }
#pragma unroll
            for (int kk = 0; kk < 4; kk++) {
                ulonglong2 wl = *(const ulonglong2*)&Wlt[(k4 + kk) * D + j0];
                ulonglong2 wr = *(const ulonglong2*)&Wrt[(k4 + kk) * D + j0];
#pragma unroll
                for (int v = 0; v < 4; v++) {
                    unsigned long long mm = pk2(mq[v][kk]);
                    unsigned long long xx = pk2(xq[v][kk]);
                    fma2(acc[v][0], mm, wl.x);
                    fma2(acc[v][1], mm, wl.y);
                    fma2(acc[v][0], xx, wr.x);
                    fma2(acc[v][1], xx, wr.y);
                }
            }
        }
        // bias + relu
        float hv[4][4];
#pragma unroll
        for (int v = 0; v < 4; v++) {
            hv[v][0] = fmaxf(lo2(acc[v][0]) + bls[j0 + 0], 0.f);
            hv[v][1] = fmaxf(hi2(acc[v][0]) + bls[j0 + 1], 0.f);
            hv[v][2] = fmaxf(lo2(acc[v][1]) + bls[j0 + 2], 0.f);
            hv[v][3] = fmaxf(hi2(acc[v][1]) + bls[j0 + 3], 0.f);
        }

        if (!HEAD) {
#pragma unroll
            for (int v = 0; v < 4; v++) {
                int n = base + g4 + v;
                if (n < N) {
                    float4 r = make_float4(hv[v][0], hv[v][1], hv[v][2], hv[v][3]);
                    *(float4*)(out + (size_t)n * D + j0) = r;
                }
            }
        } else {
            __syncthreads();
#pragma unroll
            for (int v = 0; v < 4; v++) {
                float4 r = make_float4(hv[v][0], hv[v][1], hv[v][2], hv[v][3]);
                *(float4*)&stage[(g4 + v) * D + j0] = r;
            }
            __syncthreads();

            unsigned long long ac2[4][2] = {};
            for (int k4 = 0; k4 < D; k4 += 4) {
                float hq[4][4];
#pragma unroll
                for (int v = 0; v < 4; v++) {
                    float4 t = *(const float4*)&stage[(g4 + v) * D + k4];
                    hq[v][0] = t.x; hq[v][1] = t.y; hq[v][2] = t.z; hq[v][3] = t.w;
                }
#pragma unroll
                for (int kk = 0; kk < 4; kk++) {
                    ulonglong2 wo = *(const ulonglong2*)&Wot[(k4 + kk) * D + j0];
#pragma unroll
                    for (int v = 0; v < 4; v++) {
                        unsigned long long hh = pk2(hq[v][kk]);
                        fma2(ac2[v][0], hh, wo.x);
                        fma2(ac2[v][1], hh, wo.y);
                    }
                }
            }
#pragma unroll
            for (int v = 0; v < 4; v++) {
                float l0 = lo2(ac2[v][0]) + bos[j0 + 0];
                float l1 = hi2(ac2[v][0]) + bos[j0 + 1];
                float l2 = lo2(ac2[v][1]) + bos[j0 + 2];
                float l3 = hi2(ac2[v][1]) + bos[j0 + 3];
                float mx = fmaxf(fmaxf(l0, l1), fmaxf(l2, l3));
#pragma unroll
                for (int o = 8; o; o >>= 1)
                    mx = fmaxf(mx, __shfl_xor_sync(0xffffffff, mx, o, 16));
                float sm = expf(l0 - mx) + expf(l1 - mx) + expf(l2 - mx) + expf(l3 - mx);
#pragma unroll
                for (int o = 8; o; o >>= 1)
                    sm += __shfl_xor_sync(0xffffffff, sm, o, 16);
                float lse = mx + logf(sm);
                int n = base + g4 + v;
                if (n < N) {
                    float4 r = make_float4(l0 - lse, l1 - lse, l2 - lse, l3 - lse);
                    *(float4*)(out + (size_t)n * D + j0) = r;
                }
            }
        }
    }
}

// ---------------------------------------------------------------------------
extern "C" void kernel_launch(void* const* d_in, const int* in_sizes, int n_in,
                              void* d_out, int out_size) {
    const float* x    = (const float*)d_in[0];
    const void*  ei   = d_in[1];
    const float* W1l  = (const float*)d_in[2];
    const float* b1l  = (const float*)d_in[3];
    const float* W1r  = (const float*)d_in[4];
    const float* W2l  = (const float*)d_in[5];
    const float* b2l  = (const float*)d_in[6];
    const float* W2r  = (const float*)d_in[7];
    const float* Wout = (const float*)d_in[8];
    const float* bout = (const float*)d_in[9];

    const int N = in_sizes[0] / D;
    const int E = in_sizes[1] / 2;

    int*   cnt;  cudaGetSymbolAddress((void**)&cnt,  g_cnt);
    int*   ptr;  cudaGetSymbolAddress((void**)&ptr,  g_ptr);
    int*   cur;  cudaGetSymbolAddress((void**)&cur,  g_cur);
    int*   bsum; cudaGetSymbolAddress((void**)&bsum, g_bsum);
    int*   csr;  cudaGetSymbolAddress((void**)&csr,  g_csr);
    float* mean; cudaGetSymbolAddress((void**)&mean, g_mean);
    float* h1;   cudaGetSymbolAddress((void**)&h1,   g_h1);

    const int SMEM_NH = (2 * D * D + 2 * 64 * D + 2 * D) * (int)sizeof(float);
    const int SMEM_H  = (3 * D * D + 2 * 64 * D + 2 * D) * (int)sizeof(float);

    // Opt into >48KB dynamic smem (idempotent; skip while capturing — the
    // harness's uncaptured correctness call has already set it).
    cudaStreamCaptureStatus cs = cudaStreamCaptureStatusNone;
    cudaStreamIsCapturing(0, &cs);
    if (cs == cudaStreamCaptureStatusNone) {
        cudaFuncSetAttribute(sage_transform<false>,
                             cudaFuncAttributeMaxDynamicSharedMemorySize, SMEM_NH);
        cudaFuncSetAttribute(sage_transform<true>,
                             cudaFuncAttributeMaxDynamicSharedMemorySize, SMEM_H);
    }

    // CSR build: launches [0]..[4]
    const int nb = (N + 1023) / 1024;
    const int eblocks = (E + 255) / 256;
    init_kernel<<<(N + 255) / 256, 256>>>((const int*)ei, cnt, ptr, N, E);
    hist_kernel<<<eblocks, 256>>>(ei, cnt, E);
    scan_pass1<<<nb, 256>>>(cnt, ptr, bsum, N);
    scan_fixup<<<nb, 1024>>>(ptr, bsum, cur, N);
    scatter_kernel<<<eblocks, 256>>>(ei, cur, csr, E);

    const int gblocks = (N * 16 + 255) / 256;
    const int tgrid = 304;   // 2 blocks/SM on 152 SMs

    // Layer 1: [5] gather, [6] transform
    gather_mean<<<gblocks, 256>>>(x, ptr, csr, mean, N);
    sage_transform<false><<<tgrid, 256, SMEM_NH>>>(mean, x, W1l, b1l, W1r,
                                                   nullptr, nullptr, h1, N);
    // Layer 2 + head: [7] gather, [8] transform+head
    gather_mean<<<gblocks, 256>>>(h1, ptr, csr, mean, N);
    sage_transform<true><<<tgrid, 256, SMEM_H>>>(mean, h1, W2l, b2l, W2r,
                                                 Wout, bout, (float*)d_out, N);
}

// round 4
// speedup vs baseline: 2.5103x; 1.0092x over previous
#include <cuda_runtime.h>
#include <math.h>

// GraphSAGE encoder, split-phase:
//   CSR build (3 launches: hist, single-pass scan, scatter+reset)
//   -> gather/mean kernel -> dense SAGE transform kernel
//   (layer 2 transform fuses output head + log_softmax).
// N=100000, E=1600000, D=64.
// State invariant: g_cnt and g_flag are zero at entry to each kernel_launch
// (zero-init at load; scatter_kernel re-zeroes them for the next replay).

#define MAXN 100000
#define MAXE 1600000
#define D 64

__device__ int                g_cnt[MAXN];
__device__ int                g_ptr[MAXN + 1];
__device__ int                g_cur[MAXN];
__device__ unsigned long long g_flag[128];     // scan decoupled-lookback flags
__device__ int                g_csr[MAXE];
__device__ float              g_mean[MAXN * D];
__device__ float              g_h1[MAXN * D];

// ---------------- f32x2 packed math helpers (Blackwell) ----------------
__device__ __forceinline__ unsigned long long pk2(float a) {
    unsigned long long r;
    asm("mov.b64 %0, {%1, %1};" : "=l"(r) : "f"(a));
    return r;
}
__device__ __forceinline__ void fma2(unsigned long long& d,
                                     unsigned long long a, unsigned long long b) {
    asm("fma.rn.f32x2 %0, %1, %2, %0;" : "+l"(d) : "l"(a), "l"(b));
}
__device__ __forceinline__ void add2(unsigned long long& d, unsigned long long a) {
    asm("add.rn.f32x2 %0, %0, %1;" : "+l"(d) : "l"(a));
}
__device__ __forceinline__ float lo2(unsigned long long v) {
    return __uint_as_float((unsigned)(v & 0xffffffffull));
}
__device__ __forceinline__ float hi2(unsigned long long v) {
    return __uint_as_float((unsigned)(v >> 32));
}

// Per-block edge-dtype detection: int64 values < N have zero high words.
__device__ __forceinline__ int detect_is64_block(const int* ei32) {
    __shared__ int s_is64;
    if (threadIdx.x == 0) {
        int az = 1;
#pragma unroll
        for (int t = 0; t < 8; t++) az &= (ei32[2 * t + 1] == 0);
        s_is64 = az;
    }
    __syncthreads();
    return s_is64;
}

// ---------------- CSR build ----------------
// [0] histogram of dst (cnt must be zero on entry)
__global__ void hist_kernel(const void* __restrict__ ei, int* __restrict__ cnt, int E) {
    const int is64 = detect_is64_block((const int*)ei);
    int e = blockIdx.x * blockDim.x + threadIdx.x;
    if (e >= E) return;
    int d;
    if (is64) d = (int)((const long long*)ei)[(long long)E + e];
    else      d = ((const int*)ei)[(long long)E + e];
    atomicAdd(&cnt[d], 1);
}

// [1] single-pass exclusive scan (all blocks co-resident; nb <= 128 <= 256).
// Publishes block aggregates through g_flag, parallel lookback, writes ptr+cur.
__global__ void scan_kernel(const int* __restrict__ cnt, int* __restrict__ ptr,
                            int* __restrict__ cur, unsigned long long* __restrict__ flag,
                            int N, int E) {
    __shared__ int ssum[256];
    const int tid = threadIdx.x;
    const int b = blockIdx.x;
    const int base = b * 1024 + tid * 4;

    int v0 = (base + 0 < N) ? cnt[base + 0] : 0;
    int v1 = (base + 1 < N) ? cnt[base + 1] : 0;
    int v2 = (base + 2 < N) ? cnt[base + 2] : 0;
    int v3 = (base + 3 < N) ? cnt[base + 3] : 0;
    int s = v0 + v1 + v2 + v3;
    ssum[tid] = s;
    __syncthreads();
    // Hillis-Steele inclusive scan over 256 thread sums
    for (int st = 1; st < 256; st <<= 1) {
        int t = (tid >= st) ? ssum[tid - st] : 0;
        __syncthreads();
        ssum[tid] += t;
        __syncthreads();
    }
    const int my_incl = ssum[tid];
    const int total = ssum[255];

    // publish this block's aggregate (bit0 = valid)
    if (tid == 0)
        atomicExch(&flag[b], (((unsigned long long)(unsigned)total) << 1) | 1ull);

    // parallel lookback: thread t polls predecessor t
    int agg = 0;
    if (tid < b) {
        unsigned long long f;
        do { f = atomicAdd(&flag[tid], 0ull); } while (!(f & 1ull));
        agg = (int)(f >> 1);
    }
    __syncthreads();            // everyone done with ssum (my_incl in regs)
    ssum[tid] = agg;
    __syncthreads();
    for (int st = 128; st; st >>= 1) {
        if (tid < st) ssum[tid] += ssum[tid + st];
        __syncthreads();
    }
    const int prev = ssum[0];

    int off = prev + my_incl - s;
    if (base + 0 < N) { ptr[base + 0] = off; cur[base + 0] = off; }  off += v0;
    if (base + 1 < N) { ptr[base + 1] = off; cur[base + 1] = off; }  off += v1;
    if (base + 2 < N) { ptr[base + 2] = off; cur[base + 2] = off; }  off += v2;
    if (base + 3 < N) { ptr[base + 3] = off; cur[base + 3] = off; }
    if (b == 0 && tid == 0) ptr[N] = E;
}

// [2] scatter src into CSR slots; also resets cnt/flag for the next replay.
__global__ void scatter_kernel(const void* __restrict__ ei, int* __restrict__ cur,
                               int* __restrict__ csr, int* __restrict__ cnt,
                               unsigned long long* __restrict__ flag, int N, int E) {
    const int is64 = detect_is64_block((const int*)ei);
    int e = blockIdx.x * blockDim.x + threadIdx.x;
    if (e < 128) flag[e] = 0ull;
    if (e < N) cnt[e] = 0;
    if (e >= E) return;
    int s, d;
    if (is64) {
        const long long* p = (const long long*)ei;
        s = (int)p[e];
        d = (int)p[(long long)E + e];
    } else {
        const int* p = (const int*)ei;
        s = p[e];
        d = p[(long long)E + e];
    }
    int pos = atomicAdd(&cur[d], 1);
    csr[pos] = s;
}

// ---------------- gather + mean (lean, high-occupancy, MLP-deep) ----------------
// 16 lanes per node; lane q owns feature quad [4q,4q+4). Main path: 16-neighbor
// batches, 8 loads in flight; remainder: predicated 4-wide.
__global__ void __launch_bounds__(256) gather_mean(
    const float* __restrict__ feat, const int* __restrict__ ptr,
    const int* __restrict__ csr, float* __restrict__ mean, int N)
{
    const int gid = blockIdx.x * 256 + threadIdx.x;
    const int n = gid >> 4;
    const int q = gid & 15;
    const unsigned gmask = ((threadIdx.x & 31) < 16) ? 0x0000FFFFu : 0xFFFF0000u;

    int rs = 0, re = 0;
    if (n < N) { rs = ptr[n]; re = ptr[n + 1]; }

    unsigned long long a0 = 0, a1 = 0, a2 = 0, a3 = 0;
    const float* fq = feat + q * 4;

    int b = rs;
    for (; b + 16 <= re; b += 16) {
        int idx = csr[b + q];
#pragma unroll
        for (int h = 0; h < 16; h += 8) {
            int s0 = __shfl_sync(gmask, idx, h + 0, 16);
            int s1 = __shfl_sync(gmask, idx, h + 1, 16);
            int s2 = __shfl_sync(gmask, idx, h + 2, 16);
            int s3 = __shfl_sync(gmask, idx, h + 3, 16);
            int s4 = __shfl_sync(gmask, idx, h + 4, 16);
            int s5 = __shfl_sync(gmask, idx, h + 5, 16);
            int s6 = __shfl_sync(gmask, idx, h + 6, 16);
            int s7 = __shfl_sync(gmask, idx, h + 7, 16);
            ulonglong2 v0 = *(const ulonglong2*)(fq + (size_t)s0 * D);
            ulonglong2 v1 = *(const ulonglong2*)(fq + (size_t)s1 * D);
            ulonglong2 v2 = *(const ulonglong2*)(fq + (size_t)s2 * D);
            ulonglong2 v3 = *(const ulonglong2*)(fq + (size_t)s3 * D);
            ulonglong2 v4 = *(const ulonglong2*)(fq + (size_t)s4 * D);
            ulonglong2 v5 = *(const ulonglong2*)(fq + (size_t)s5 * D);
            ulonglong2 v6 = *(const ulonglong2*)(fq + (size_t)s6 * D);
            ulonglong2 v7 = *(const ulonglong2*)(fq + (size_t)s7 * D);
            add2(a0, v0.x); add2(a1, v0.y);
            add2(a2, v1.x); add2(a3, v1.y);
            add2(a0, v2.x); add2(a1, v2.y);
            add2(a2, v3.x); add2(a3, v3.y);
            add2(a0, v4.x); add2(a1, v4.y);
            add2(a2, v5.x); add2(a3, v5.y);
            add2(a0, v6.x); add2(a1, v6.y);
            add2(a2, v7.x); add2(a3, v7.y);
        }
    }
    const int cnt = re - b;
    if (cnt > 0) {
        int idx = (b + q < re) ? csr[b + q] : 0;
#pragma unroll
        for (int j = 0; j < 16; j += 4) {
            if (j < cnt) {
                int s0 = __shfl_sync(gmask, idx, j + 0, 16);
                int s1 = __shfl_sync(gmask, idx, j + 1, 16);
                int s2 = __shfl_sync(gmask, idx, j + 2, 16);
                int s3 = __shfl_sync(gmask, idx, j + 3, 16);
                ulonglong2 v0 = *(const ulonglong2*)(fq + (size_t)s0 * D);
                add2(a0, v0.x); add2(a1, v0.y);
                if (j + 1 < cnt) {
                    ulonglong2 v1 = *(const ulonglong2*)(fq + (size_t)s1 * D);
                    add2(a2, v1.x); add2(a3, v1.y);
                }
                if (j + 2 < cnt) {
                    ulonglong2 v2 = *(const ulonglong2*)(fq + (size_t)s2 * D);
                    add2(a0, v2.x); add2(a1, v2.y);
                }
                if (j + 3 < cnt) {
                    ulonglong2 v3 = *(const ulonglong2*)(fq + (size_t)s3 * D);
                    add2(a2, v3.x); add2(a3, v3.y);
                }
            }
        }
    }

    if (n < N) {
        add2(a0, a2);
        add2(a1, a3);
        const float invd = 1.0f / fmaxf((float)(re - rs), 1.0f);
        float4 r;
        r.x = lo2(a0) * invd; r.y = hi2(a0) * invd;
        r.z = lo2(a1) * invd; r.w = hi2(a1) * invd;
        *(float4*)(mean + (size_t)n * D + q * 4) = r;
    }
}

// ---------------- dense SAGE transform (G=4 nodes/group, FFMA2) ----------------
// h = relu(mean @ Wl^T + bl + x @ Wr^T); HEAD: out = log_softmax(h @ Wo^T + bo).
// Block 256 = 16 groups x 16 lanes; group owns 4 nodes; lane owns output quad.
template<bool HEAD>
__global__ void __launch_bounds__(256) sage_transform(
    const float* __restrict__ mean, const float* __restrict__ x,
    const float* __restrict__ Wl, const float* __restrict__ bl,
    const float* __restrict__ Wr,
    const float* __restrict__ Wo, const float* __restrict__ bo,
    float* __restrict__ out, int N)
{
    extern __shared__ float smf[];
    float* Wlt   = smf;                              // [64][64] transposed
    float* Wrt   = Wlt + D * D;
    float* Wot   = Wrt + D * D;                      // HEAD only
    float* stage = Wot + (HEAD ? D * D : 0);         // [64][64] mean, then h
    float* xst   = stage + 64 * D;                   // [64][64] x
    float* bls   = xst + 64 * D;
    float* bos   = bls + D;

    const int tid = threadIdx.x;
#pragma unroll
    for (int it = 0; it < 4; it++) {
        int i = tid + it * 256;          // 1024 quad slots
        int r = i & 63;
        int c0 = (i >> 6) * 4;
        float4 w = *(const float4*)&Wl[r * D + c0];
        Wlt[(c0 + 0) * D + r] = w.x; Wlt[(c0 + 1) * D + r] = w.y;
        Wlt[(c0 + 2) * D + r] = w.z; Wlt[(c0 + 3) * D + r] = w.w;
        w = *(const float4*)&Wr[r * D + c0];
        Wrt[(c0 + 0) * D + r] = w.x; Wrt[(c0 + 1) * D + r] = w.y;
        Wrt[(c0 + 2) * D + r] = w.z; Wrt[(c0 + 3) * D + r] = w.w;
        if (HEAD) {
            w = *(const float4*)&Wo[r * D + c0];
            Wot[(c0 + 0) * D + r] = w.x; Wot[(c0 + 1) * D + r] = w.y;
            Wot[(c0 + 2) * D + r] = w.z; Wot[(c0 + 3) * D + r] = w.w;
        }
    }
    if (tid < D) { bls[tid] = bl[tid]; if (HEAD) bos[tid] = bo[tid]; }

    const int g4 = (tid >> 4) * 4;       // first of this group's 4 node rows
    const int q = tid & 15;
    const int j0 = q * 4;
    const int ntiles = (N + 63) / 64;

    for (int tile = blockIdx.x; tile < ntiles; tile += gridDim.x) {
        const int base = tile * 64;
        __syncthreads();
#pragma unroll
        for (int it = 0; it < 4; it++) {
            int i = tid + it * 256;
            int row = i >> 4, qq = (i & 15) * 4;
            int nidx = base + row;
            float4 mv = make_float4(0.f, 0.f, 0.f, 0.f), xv = mv;
            if (nidx < N) {
                mv = *(const float4*)(mean + (size_t)nidx * D + qq);
                xv = *(const float4*)(x    + (size_t)nidx * D + qq);
            }
            *(float4*)&stage[row * D + qq] = mv;
            *(float4*)&xst[row * D + qq]   = xv;
        }
        __syncthreads();

        unsigned long long acc[4][2] = {};
        for (int k4 = 0; k4 < D; k4 += 4) {
            float mq[4][4], xq[4][4];
#pragma unroll
            for (int v = 0; v < 4; v++) {
                float4 t = *(const float4*)&stage[(g4 + v) * D + k4];
                mq[v][0] = t.x; mq[v][1] = t.y; mq[v][2] = t.z; mq[v][3] = t.w;
                t = *(const float4*)&xst[(g4 + v) * D + k4];
                xq[v][0] = t.x; xq[v][1] = t.y; xq[v][2] = t.z; xq[v][3] = t.w;
            }
#pragma unroll
            for (int kk = 0; kk < 4; kk++) {
                ulonglong2 wl = *(const ulonglong2*)&Wlt[(k4 + kk) * D + j0];
                ulonglong2 wr = *(const ulonglong2*)&Wrt[(k4 + kk) * D + j0];
#pragma unroll
                for (int v = 0; v < 4; v++) {
                    unsigned long long mm = pk2(mq[v][kk]);
                    unsigned long long xx = pk2(xq[v][kk]);
                    fma2(acc[v][0], mm, wl.x);
                    fma2(acc[v][1], mm, wl.y);
                    fma2(acc[v][0], xx, wr.x);
                    fma2(acc[v][1], xx, wr.y);
                }
            }
        }
        float hv[4][4];
#pragma unroll
        for (int v = 0; v < 4; v++) {
            hv[v][0] = fmaxf(lo2(acc[v][0]) + bls[j0 + 0], 0.f);
            hv[v][1] = fmaxf(hi2(acc[v][0]) + bls[j0 + 1], 0.f);
            hv[v][2] = fmaxf(lo2(acc[v][1]) + bls[j0 + 2], 0.f);
            hv[v][3] = fmaxf(hi2(acc[v][1]) + bls[j0 + 3], 0.f);
        }

        if (!HEAD) {
#pragma unroll
            for (int v = 0; v < 4; v++) {
                int n = base + g4 + v;
                if (n < N) {
                    float4 r = make_float4(hv[v][0], hv[v][1], hv[v][2], hv[v][3]);
                    *(float4*)(out + (size_t)n * D + j0) = r;
                }
            }
        } else {
            __syncthreads();
#pragma unroll
            for (int v = 0; v < 4; v++) {
                float4 r = make_float4(hv[v][0], hv[v][1], hv[v][2], hv[v][3]);
                *(float4*)&stage[(g4 + v) * D + j0] = r;
            }
            __syncthreads();

            unsigned long long ac2[4][2] = {};
            for (int k4 = 0; k4 < D; k4 += 4) {
                float hq[4][4];
#pragma unroll
                for (int v = 0; v < 4; v++) {
                    float4 t = *(const float4*)&stage[(g4 + v) * D + k4];
                    hq[v][0] = t.x; hq[v][1] = t.y; hq[v][2] = t.z; hq[v][3] = t.w;
                }
#pragma unroll
                for (int kk = 0; kk < 4; kk++) {
                    ulonglong2 wo = *(const ulonglong2*)&Wot[(k4 + kk) * D + j0];
#pragma unroll
                    for (int v = 0; v < 4; v++) {
                        unsigned long long hh = pk2(hq[v][kk]);
                        fma2(ac2[v][0], hh, wo.x);
                        fma2(ac2[v][1], hh, wo.y);
                    }
                }
            }
#pragma unroll
            for (int v = 0; v < 4; v++) {
                float l0 = lo2(ac2[v][0]) + bos[j0 + 0];
                float l1 = hi2(ac2[v][0]) + bos[j0 + 1];
                float l2 = lo2(ac2[v][1]) + bos[j0 + 2];
                float l3 = hi2(ac2[v][1]) + bos[j0 + 3];
                float mx = fmaxf(fmaxf(l0, l1), fmaxf(l2, l3));
#pragma unroll
                for (int o = 8; o; o >>= 1)
                    mx = fmaxf(mx, __shfl_xor_sync(0xffffffff, mx, o, 16));
                float sm = expf(l0 - mx) + expf(l1 - mx) + expf(l2 - mx) + expf(l3 - mx);
#pragma unroll
                for (int o = 8; o; o >>= 1)
                    sm += __shfl_xor_sync(0xffffffff, sm, o, 16);
                float lse = mx + logf(sm);
                int n = base + g4 + v;
                if (n < N) {
                    float4 r = make_float4(l0 - lse, l1 - lse, l2 - lse, l3 - lse);
                    *(float4*)(out + (size_t)n * D + j0) = r;
                }
            }
        }
    }
}

// ---------------------------------------------------------------------------
extern "C" void kernel_launch(void* const* d_in, const int* in_sizes, int n_in,
                              void* d_out, int out_size) {
    const float* x    = (const float*)d_in[0];
    const void*  ei   = d_in[1];
    const float* W1l  = (const float*)d_in[2];
    const float* b1l  = (const float*)d_in[3];
    const float* W1r  = (const float*)d_in[4];
    const float* W2l  = (const float*)d_in[5];
    const float* b2l  = (const float*)d_in[6];
    const float* W2r  = (const float*)d_in[7];
    const float* Wout = (const float*)d_in[8];
    const float* bout = (const float*)d_in[9];

    const int N = in_sizes[0] / D;
    const int E = in_sizes[1] / 2;

    int*   cnt;  cudaGetSymbolAddress((void**)&cnt,  g_cnt);
    int*   ptr;  cudaGetSymbolAddress((void**)&ptr,  g_ptr);
    int*   cur;  cudaGetSymbolAddress((void**)&cur,  g_cur);
    unsigned long long* flag; cudaGetSymbolAddress((void**)&flag, g_flag);
    int*   csr;  cudaGetSymbolAddress((void**)&csr,  g_csr);
    float* mean; cudaGetSymbolAddress((void**)&mean, g_mean);
    float* h1;   cudaGetSymbolAddress((void**)&h1,   g_h1);

    const int SMEM_NH = (2 * D * D + 2 * 64 * D + 2 * D) * (int)sizeof(float);
    const int SMEM_H  = (3 * D * D + 2 * 64 * D + 2 * D) * (int)sizeof(float);

    // Opt into >48KB dynamic smem (skip while capturing; the uncaptured
    // correctness call has already applied it).
    cudaStreamCaptureStatus cs = cudaStreamCaptureStatusNone;
    cudaStreamIsCapturing(0, &cs);
    if (cs == cudaStreamCaptureStatusNone) {
        cudaFuncSetAttribute(sage_transform<false>,
                             cudaFuncAttributeMaxDynamicSharedMemorySize, SMEM_NH);
        cudaFuncSetAttribute(sage_transform<true>,
                             cudaFuncAttributeMaxDynamicSharedMemorySize, SMEM_H);
    }

    const int nb = (N + 1023) / 1024;          // 98 scan blocks (co-resident)
    const int eblocks = (E + 255) / 256;
    const int gblocks = (N * 16 + 255) / 256;
    const int tgrid = 304;                      // 2 blocks/SM on 152 SMs

    // CSR build: [0] hist, [1] scan, [2] scatter(+state reset)
    hist_kernel<<<eblocks, 256>>>(ei, cnt, E);
    scan_kernel<<<nb, 256>>>(cnt, ptr, cur, flag, N, E);
    scatter_kernel<<<eblocks, 256>>>(ei, cur, csr, cnt, flag, N, E);

    // Layer 1: [3] gather (profiled), [4] transform
    gather_mean<<<gblocks, 256>>>(x, ptr, csr, mean, N);
    sage_transform<false><<<tgrid, 256, SMEM_NH>>>(mean, x, W1l, b1l, W1r,
                                                   nullptr, nullptr, h1, N);
    // Layer 2 + head: [5] gather, [6] transform+head
    gather_mean<<<gblocks, 256>>>(h1, ptr, csr, mean, N);
    sage_transform<true><<<tgrid, 256, SMEM_H>>>(mean, h1, W2l, b2l, W2r,
                                                 Wout, bout, (float*)d_out, N);
}

// round 5
// speedup vs baseline: 2.7356x; 1.0897x over previous
#include <cuda_runtime.h>
#include <cuda_fp16.h>
#include <math.h>

// GraphSAGE encoder, split-phase, fp16 gather path:
//   CSR build (3 launches: hist+x->fp16, single-pass scan, scatter+reset)
//   -> gather/mean (fp16 rows, fp32 accum) -> dense SAGE transform (fp32 math)
//   (layer 1 transform writes h1 in fp16; layer 2 fuses head + log_softmax).
// N=100000, E=1600000, D=64.
// State invariant: g_cnt and g_flag are zero at entry to each kernel_launch
// (zero-init at load; scatter_kernel re-zeroes them for the next replay).

#define MAXN 100000
#define MAXE 1600000
#define D 64

__device__ int                g_cnt[MAXN];
__device__ int                g_ptr[MAXN + 1];
__device__ int                g_cur[MAXN];
__device__ unsigned long long g_flag[128];     // scan decoupled-lookback flags
__device__ int                g_csr[MAXE];
__device__ float              g_mean[MAXN * D];
__device__ __half             g_xh[MAXN * D];  // fp16 copy of x (gather source)
__device__ __half             g_h1[MAXN * D];  // layer-1 activations (fp16)

// ---------------- f32x2 packed math helpers (Blackwell) ----------------
__device__ __forceinline__ unsigned long long pk2(float a) {
    unsigned long long r;
    asm("mov.b64 %0, {%1, %1};" : "=l"(r) : "f"(a));
    return r;
}
__device__ __forceinline__ void fma2(unsigned long long& d,
                                     unsigned long long a, unsigned long long b) {
    asm("fma.rn.f32x2 %0, %1, %2, %0;" : "+l"(d) : "l"(a), "l"(b));
}
__device__ __forceinline__ float lo2(unsigned long long v) {
    return __uint_as_float((unsigned)(v & 0xffffffffull));
}
__device__ __forceinline__ float hi2(unsigned long long v) {
    return __uint_as_float((unsigned)(v >> 32));
}

// fp16 quad helpers
__device__ __forceinline__ void acc4h(float& a0, float& a1, float& a2, float& a3,
                                      uint2 v) {
    float2 f0 = __half22float2(*reinterpret_cast<const __half2*>(&v.x));
    float2 f1 = __half22float2(*reinterpret_cast<const __half2*>(&v.y));
    a0 += f0.x; a1 += f0.y; a2 += f1.x; a3 += f1.y;
}
__device__ __forceinline__ float4 ld4h(const __half* p) {
    uint2 v = *reinterpret_cast<const uint2*>(p);
    float2 f0 = __half22float2(*reinterpret_cast<const __half2*>(&v.x));
    float2 f1 = __half22float2(*reinterpret_cast<const __half2*>(&v.y));
    return make_float4(f0.x, f0.y, f1.x, f1.y);
}
__device__ __forceinline__ void st4h(__half* p, float x, float y, float z, float w) {
    __half2 h0 = __floats2half2_rn(x, y);
    __half2 h1 = __floats2half2_rn(z, w);
    uint2 u;
    u.x = *reinterpret_cast<unsigned*>(&h0);
    u.y = *reinterpret_cast<unsigned*>(&h1);
    *reinterpret_cast<uint2*>(p) = u;
}

// Per-block edge-dtype detection: int64 values < N have zero high words.
__device__ __forceinline__ int detect_is64_block(const int* ei32) {
    __shared__ int s_is64;
    if (threadIdx.x == 0) {
        int az = 1;
#pragma unroll
        for (int t = 0; t < 8; t++) az &= (ei32[2 * t + 1] == 0);
        s_is64 = az;
    }
    __syncthreads();
    return s_is64;
}

// ---------------- CSR build ----------------
// [0] histogram of dst (cnt zero on entry) + x -> fp16 conversion
__global__ void hist_kernel(const void* __restrict__ ei, int* __restrict__ cnt,
                            const float* __restrict__ x, __half* __restrict__ xh,
                            int nquads, int E) {
    const int is64 = detect_is64_block((const int*)ei);
    const int e = blockIdx.x * blockDim.x + threadIdx.x;
    const int stride = gridDim.x * blockDim.x;
    for (int i = e; i < nquads; i += stride) {
        float4 v = reinterpret_cast<const float4*>(x)[i];
        st4h(xh + (size_t)i * 4, v.x, v.y, v.z, v.w);
    }
    if (e >= E) return;
    int d;
    if (is64) d = (int)((const long long*)ei)[(long long)E + e];
    else      d = ((const int*)ei)[(long long)E + e];
    atomicAdd(&cnt[d], 1);
}

// [1] single-pass exclusive scan (all blocks co-resident; nb <= 128).
__global__ void scan_kernel(const int* __restrict__ cnt, int* __restrict__ ptr,
                            int* __restrict__ cur, unsigned long long* __restrict__ flag,
                            int N, int E) {
    __shared__ int ssum[256];
    const int tid = threadIdx.x;
    const int b = blockIdx.x;
    const int base = b * 1024 + tid * 4;

    int v0 = (base + 0 < N) ? cnt[base + 0] : 0;
    int v1 = (base + 1 < N) ? cnt[base + 1] : 0;
    int v2 = (base + 2 < N) ? cnt[base + 2] : 0;
    int v3 = (base + 3 < N) ? cnt[base + 3] : 0;
    int s = v0 + v1 + v2 + v3;
    ssum[tid] = s;
    __syncthreads();
    for (int st = 1; st < 256; st <<= 1) {
        int t = (tid >= st) ? ssum[tid - st] : 0;
        __syncthreads();
        ssum[tid] += t;
        __syncthreads();
    }
    const int my_incl = ssum[tid];
    const int total = ssum[255];

    if (tid == 0)
        atomicExch(&flag[b], (((unsigned long long)(unsigned)total) << 1) | 1ull);

    int agg = 0;
    if (tid < b) {
        unsigned long long f;
        do { f = atomicAdd(&flag[tid], 0ull); } while (!(f & 1ull));
        agg = (int)(f >> 1);
    }
    __syncthreads();
    ssum[tid] = agg;
    __syncthreads();
    for (int st = 128; st; st >>= 1) {
        if (tid < st) ssum[tid] += ssum[tid + st];
        __syncthreads();
    }
    const int prev = ssum[0];

    int off = prev + my_incl - s;
    if (base + 0 < N) { ptr[base + 0] = off; cur[base + 0] = off; }  off += v0;
    if (base + 1 < N) { ptr[base + 1] = off; cur[base + 1] = off; }  off += v1;
    if (base + 2 < N) { ptr[base + 2] = off; cur[base + 2] = off; }  off += v2;
    if (base + 3 < N) { ptr[base + 3] = off; cur[base + 3] = off; }
    if (b == 0 && tid == 0) ptr[N] = E;
}

// [2] scatter src into CSR slots; resets cnt/flag for the next replay.
__global__ void scatter_kernel(const void* __restrict__ ei, int* __restrict__ cur,
                               int* __restrict__ csr, int* __restrict__ cnt,
                               unsigned long long* __restrict__ flag, int N, int E) {
    const int is64 = detect_is64_block((const int*)ei);
    int e = blockIdx.x * blockDim.x + threadIdx.x;
    if (e < 128) flag[e] = 0ull;
    if (e < N) cnt[e] = 0;
    if (e >= E) return;
    int s, d;
    if (is64) {
        const long long* p = (const long long*)ei;
        s = (int)p[e];
        d = (int)p[(long long)E + e];
    } else {
        const int* p = (const int*)ei;
        s = p[e];
        d = p[(long long)E + e];
    }
    int pos = atomicAdd(&cur[d], 1);
    csr[pos] = s;
}

// ---------------- gather + mean (fp16 rows, fp32 accumulation) ----------------
// 16 lanes per node; lane q owns feature quad [4q,4q+4) = 8 bytes fp16.
// One edge = 16 x LDG.64 = 128B = one L2 line. Main path MLP 8, remainder MLP 4.
__global__ void __launch_bounds__(256) gather_mean(
    const __half* __restrict__ feat, const int* __restrict__ ptr,
    const int* __restrict__ csr, float* __restrict__ mean, int N)
{
    const int gid = blockIdx.x * 256 + threadIdx.x;
    const int n = gid >> 4;
    const int q = gid & 15;
    const unsigned gmask = ((threadIdx.x & 31) < 16) ? 0x0000FFFFu : 0xFFFF0000u;

    int rs = 0, re = 0;
    if (n < N) { rs = ptr[n]; re = ptr[n + 1]; }

    float a0 = 0.f, a1 = 0.f, a2 = 0.f, a3 = 0.f;
    const __half* fq = feat + q * 4;

    int b = rs;
    for (; b + 16 <= re; b += 16) {
        int idx = csr[b + q];
#pragma unroll
        for (int h = 0; h < 16; h += 8) {
            int s0 = __shfl_sync(gmask, idx, h + 0, 16);
            int s1 = __shfl_sync(gmask, idx, h + 1, 16);
            int s2 = __shfl_sync(gmask, idx, h + 2, 16);
            int s3 = __shfl_sync(gmask, idx, h + 3, 16);
            int s4 = __shfl_sync(gmask, idx, h + 4, 16);
            int s5 = __shfl_sync(gmask, idx, h + 5, 16);
            int s6 = __shfl_sync(gmask, idx, h + 6, 16);
            int s7 = __shfl_sync(gmask, idx, h + 7, 16);
            uint2 v0 = *(const uint2*)(fq + (size_t)s0 * D);
            uint2 v1 = *(const uint2*)(fq + (size_t)s1 * D);
            uint2 v2 = *(const uint2*)(fq + (size_t)s2 * D);
            uint2 v3 = *(const uint2*)(fq + (size_t)s3 * D);
            uint2 v4 = *(const uint2*)(fq + (size_t)s4 * D);
            uint2 v5 = *(const uint2*)(fq + (size_t)s5 * D);
            uint2 v6 = *(const uint2*)(fq + (size_t)s6 * D);
            uint2 v7 = *(const uint2*)(fq + (size_t)s7 * D);
            acc4h(a0, a1, a2, a3, v0);
            acc4h(a0, a1, a2, a3, v1);
            acc4h(a0, a1, a2, a3, v2);
            acc4h(a0, a1, a2, a3, v3);
            acc4h(a0, a1, a2, a3, v4);
            acc4h(a0, a1, a2, a3, v5);
            acc4h(a0, a1, a2, a3, v6);
            acc4h(a0, a1, a2, a3, v7);
        }
    }
    const int cnt = re - b;
    if (cnt > 0) {
        int idx = (b + q < re) ? csr[b + q] : 0;
#pragma unroll
        for (int j = 0; j < 16; j += 4) {
            if (j < cnt) {
                int s0 = __shfl_sync(gmask, idx, j + 0, 16);
                int s1 = __shfl_sync(gmask, idx, j + 1, 16);
                int s2 = __shfl_sync(gmask, idx, j + 2, 16);
                int s3 = __shfl_sync(gmask, idx, j + 3, 16);
                uint2 v0 = *(const uint2*)(fq + (size_t)s0 * D);
                acc4h(a0, a1, a2, a3, v0);
                if (j + 1 < cnt) {
                    uint2 v1 = *(const uint2*)(fq + (size_t)s1 * D);
                    acc4h(a0, a1, a2, a3, v1);
                }
                if (j + 2 < cnt) {
                    uint2 v2 = *(const uint2*)(fq + (size_t)s2 * D);
                    acc4h(a0, a1, a2, a3, v2);
                }
                if (j + 3 < cnt) {
                    uint2 v3 = *(const uint2*)(fq + (size_t)s3 * D);
                    acc4h(a0, a1, a2, a3, v3);
                }
            }
        }
    }

    if (n < N) {
        const float invd = 1.0f / fmaxf((float)(re - rs), 1.0f);
        float4 r = make_float4(a0 * invd, a1 * invd, a2 * invd, a3 * invd);
        *(float4*)(mean + (size_t)n * D + q * 4) = r;
    }
}

// ---------------- dense SAGE transform (G=4 nodes/group, FFMA2) ----------------
// h = relu(mean @ Wl^T + bl + x @ Wr^T); HEAD: out = log_softmax(h @ Wo^T + bo).
// XH: x input is fp16. !HEAD writes fp16 h; HEAD writes fp32 log-probs.
template<bool HEAD, bool XH>
__global__ void __launch_bounds__(256) sage_transform(
    const float* __restrict__ mean, const void* __restrict__ x,
    const float* __restrict__ Wl, const float* __restrict__ bl,
    const float* __restrict__ Wr,
    const float* __restrict__ Wo, const float* __restrict__ bo,
    void* __restrict__ out, int N)
{
    extern __shared__ float smf[];
    float* Wlt   = smf;                              // [64][64] transposed
    float* Wrt   = Wlt + D * D;
    float* Wot   = Wrt + D * D;                      // HEAD only
    float* stage = Wot + (HEAD ? D * D : 0);         // [64][64] mean, then h
    float* xst   = stage + 64 * D;                   // [64][64] x
    float* bls   = xst + 64 * D;
    float* bos   = bls + D;

    const int tid = threadIdx.x;
#pragma unroll
    for (int it = 0; it < 4; it++) {
        int i = tid + it * 256;          // 1024 quad slots
        int r = i & 63;
        int c0 = (i >> 6) * 4;
        float4 w = *(const float4*)&Wl[r * D + c0];
        Wlt[(c0 + 0) * D + r] = w.x; Wlt[(c0 + 1) * D + r] = w.y;
        Wlt[(c0 + 2) * D + r] = w.z; Wlt[(c0 + 3) * D + r] = w.w;
        w = *(const float4*)&Wr[r * D + c0];
        Wrt[(c0 + 0) * D + r] = w.x; Wrt[(c0 + 1) * D + r] = w.y;
        Wrt[(c0 + 2) * D + r] = w.z; Wrt[(c0 + 3) * D + r] = w.w;
        if (HEAD) {
            w = *(const float4*)&Wo[r * D + c0];
            Wot[(c0 + 0) * D + r] = w.x; Wot[(c0 + 1) * D + r] = w.y;
            Wot[(c0 + 2) * D + r] = w.z; Wot[(c0 + 3) * D + r] = w.w;
        }
    }
    if (tid < D) { bls[tid] = bl[tid]; if (HEAD) bos[tid] = bo[tid]; }

    const int g4 = (tid >> 4) * 4;       // first of this group's 4 node rows
    const int q = tid & 15;
    const int j0 = q * 4;
    const int ntiles = (N + 63) / 64;

    for (int tile = blockIdx.x; tile < ntiles; tile += gridDim.x) {
        const int base = tile * 64;
        __syncthreads();
#pragma unroll
        for (int it = 0; it < 4; it++) {
            int i = tid + it * 256;
            int row = i >> 4, qq = (i & 15) * 4;
            int nidx = base + row;
            float4 mv = make_float4(0.f, 0.f, 0.f, 0.f), xv = mv;
            if (nidx < N) {
                mv = *(const float4*)(mean + (size_t)nidx * D + qq);
                if (XH) xv = ld4h((const __half*)x + (size_t)nidx * D + qq);
                else    xv = *(const float4*)((const float*)x + (size_t)nidx * D + qq);
            }
            *(float4*)&stage[row * D + qq] = mv;
            *(float4*)&xst[row * D + qq]   = xv;
        }
        __syncthreads();

        unsigned long long acc[4][2] = {};
        for (int k4 = 0; k4 < D; k4 += 4) {
            float mq[4][4], xq[4][4];
#pragma unroll
            for (int v = 0; v < 4; v++) {
                float4 t = *(const float4*)&stage[(g4 + v) * D + k4];
                mq[v][0] = t.x; mq[v][1] = t.y; mq[v][2] = t.z; mq[v][3] = t.w;
                t = *(const float4*)&xst[(g4 + v) * D + k4];
                xq[v][0] = t.x; xq[v][1] = t.y; xq[v][2] = t.z; xq[v][3] = t.w;
            }
#pragma unroll
            for (int kk = 0; kk < 4; kk++) {
                ulonglong2 wl = *(const ulonglong2*)&Wlt[(k4 + kk) * D + j0];
                ulonglong2 wr = *(const ulonglong2*)&Wrt[(k4 + kk) * D + j0];
#pragma unroll
                for (int v = 0; v < 4; v++) {
                    unsigned long long mm = pk2(mq[v][kk]);
                    unsigned long long xx = pk2(xq[v][kk]);
                    fma2(acc[v][0], mm, wl.x);
                    fma2(acc[v][1], mm, wl.y);
                    fma2(acc[v][0], xx, wr.x);
                    fma2(acc[v][1], xx, wr.y);
                }
            }
        }
        float hv[4][4];
#pragma unroll
        for (int v = 0; v < 4; v++) {
            hv[v][0] = fmaxf(lo2(acc[v][0]) + bls[j0 + 0], 0.f);
            hv[v][1] = fmaxf(hi2(acc[v][0]) + bls[j0 + 1], 0.f);
            hv[v][2] = fmaxf(lo2(acc[v][1]) + bls[j0 + 2], 0.f);
            hv[v][3] = fmaxf(hi2(acc[v][1]) + bls[j0 + 3], 0.f);
        }

        if (!HEAD) {
#pragma unroll
            for (int v = 0; v < 4; v++) {
                int n = base + g4 + v;
                if (n < N)
                    st4h((__half*)out + (size_t)n * D + j0,
                         hv[v][0], hv[v][1], hv[v][2], hv[v][3]);
            }
        } else {
            __syncthreads();
#pragma unroll
            for (int v = 0; v < 4; v++) {
                float4 r = make_float4(hv[v][0], hv[v][1], hv[v][2], hv[v][3]);
                *(float4*)&stage[(g4 + v) * D + j0] = r;
            }
            __syncthreads();

            unsigned long long ac2[4][2] = {};
            for (int k4 = 0; k4 < D; k4 += 4) {
                float hq[4][4];
#pragma unroll
                for (int v = 0; v < 4; v++) {
                    float4 t = *(const float4*)&stage[(g4 + v) * D + k4];
                    hq[v][0] = t.x; hq[v][1] = t.y; hq[v][2] = t.z; hq[v][3] = t.w;
                }
#pragma unroll
                for (int kk = 0; kk < 4; kk++) {
                    ulonglong2 wo = *(const ulonglong2*)&Wot[(k4 + kk) * D + j0];
#pragma unroll
                    for (int v = 0; v < 4; v++) {
                        unsigned long long hh = pk2(hq[v][kk]);
                        fma2(ac2[v][0], hh, wo.x);
                        fma2(ac2[v][1], hh, wo.y);
                    }
                }
            }
#pragma unroll
            for (int v = 0; v < 4; v++) {
                float l0 = lo2(ac2[v][0]) + bos[j0 + 0];
                float l1 = hi2(ac2[v][0]) + bos[j0 + 1];
                float l2 = lo2(ac2[v][1]) + bos[j0 + 2];
                float l3 = hi2(ac2[v][1]) + bos[j0 + 3];
                float mx = fmaxf(fmaxf(l0, l1), fmaxf(l2, l3));
#pragma unroll
                for (int o = 8; o; o >>= 1)
                    mx = fmaxf(mx, __shfl_xor_sync(0xffffffff, mx, o, 16));
                float sm = expf(l0 - mx) + expf(l1 - mx) + expf(l2 - mx) + expf(l3 - mx);
#pragma unroll
                for (int o = 8; o; o >>= 1)
                    sm += __shfl_xor_sync(0xffffffff, sm, o, 16);
                float lse = mx + logf(sm);
                int n = base + g4 + v;
                if (n < N) {
                    float4 r = make_float4(l0 - lse, l1 - lse, l2 - lse, l3 - lse);
                    *(float4*)((float*)out + (size_t)n * D + j0) = r;
                }
            }
        }
    }
}

// ---------------------------------------------------------------------------
extern "C" void kernel_launch(void* const* d_in, const int* in_sizes, int n_in,
                              void* d_out, int out_size) {
    const float* x    = (const float*)d_in[0];
    const void*  ei   = d_in[1];
    const float* W1l  = (const float*)d_in[2];
    const float* b1l  = (const float*)d_in[3];
    const float* W1r  = (const float*)d_in[4];
    const float* W2l  = (const float*)d_in[5];
    const float* b2l  = (const float*)d_in[6];
    const float* W2r  = (const float*)d_in[7];
    const float* Wout = (const float*)d_in[8];
    const float* bout = (const float*)d_in[9];

    const int N = in_sizes[0] / D;
    const int E = in_sizes[1] / 2;

    int*   cnt;  cudaGetSymbolAddress((void**)&cnt,  g_cnt);
    int*   ptr;  cudaGetSymbolAddress((void**)&ptr,  g_ptr);
    int*   cur;  cudaGetSymbolAddress((void**)&cur,  g_cur);
    unsigned long long* flag; cudaGetSymbolAddress((void**)&flag, g_flag);
    int*   csr;  cudaGetSymbolAddress((void**)&csr,  g_csr);
    float* mean; cudaGetSymbolAddress((void**)&mean, g_mean);
    __half* xh;  cudaGetSymbolAddress((void**)&xh,   g_xh);
    __half* h1;  cudaGetSymbolAddress((void**)&h1,   g_h1);

    const int SMEM_NH = (2 * D * D + 2 * 64 * D + 2 * D) * (int)sizeof(float);
    const int SMEM_H  = (3 * D * D + 2 * 64 * D + 2 * D) * (int)sizeof(float);

    // Opt into >48KB dynamic smem (skip while capturing; the uncaptured
    // correctness call has already applied it).
    cudaStreamCaptureStatus cs = cudaStreamCaptureStatusNone;
    cudaStreamIsCapturing(0, &cs);
    if (cs == cudaStreamCaptureStatusNone) {
        cudaFuncSetAttribute(sage_transform<false, false>,
                             cudaFuncAttributeMaxDynamicSharedMemorySize, SMEM_NH);
        cudaFuncSetAttribute(sage_transform<true, true>,
                             cudaFuncAttributeMaxDynamicSharedMemorySize, SMEM_H);
    }

    const int nb = (N + 1023) / 1024;          // 98 scan blocks (co-resident)
    const int eblocks = (E + 255) / 256;
    const int gblocks = (N * 16 + 255) / 256;
    const int tgrid = 304;                      // 2 blocks/SM on 152 SMs

    // CSR build: [0] hist + x->fp16, [1] scan, [2] scatter(+state reset)
    hist_kernel<<<eblocks, 256>>>(ei, cnt, x, xh, N * D / 4, E);
    scan_kernel<<<nb, 256>>>(cnt, ptr, cur, flag, N, E);
    scatter_kernel<<<eblocks, 256>>>(ei, cur, csr, cnt, flag, N, E);

    // Layer 1: [3] gather (profiled), [4] transform (writes fp16 h1)
    gather_mean<<<gblocks, 256>>>(xh, ptr, csr, mean, N);
    sage_transform<false, false><<<tgrid, 256, SMEM_NH>>>(
        mean, x, W1l, b1l, W1r, nullptr, nullptr, h1, N);
    // Layer 2 + head: [5] gather, [6] transform+head
    gather_mean<<<gblocks, 256>>>(h1, ptr, csr, mean, N);
    sage_transform<true, true><<<tgrid, 256, SMEM_H>>>(
        mean, h1, W2l, b2l, W2r, Wout, bout, (float*)d_out, N);
}

// round 8
// speedup vs baseline: 3.8932x; 1.4232x over previous
#include <cuda_runtime.h>
#include <cuda_fp16.h>
#include <math.h>
#include <stdint.h>

// GraphSAGE encoder:
//   CSR build (3 launches) -> fp16 gather/mean -> HMMA (mma.sync m16n8k16)
//   transform (layer 2 fuses output head GEMM + log_softmax).
// NOTE: tcgen05 is unusable here — harness ptxas targets sm_103 (no 'a'),
// so tensor work goes through baseline mma.sync/ldmatrix instead.
// N=100000, E=1600000, D=64.
// State invariant: g_cnt and g_flag are zero at entry to each kernel_launch
// (zero-init at load; scatter_kernel re-zeroes them for the next replay).

#define MAXN 100000
#define MAXE 1600000
#define D 64

__device__ int                g_cnt[MAXN];
__device__ int                g_ptr[MAXN + 1];
__device__ int                g_cur[MAXN];
__device__ unsigned long long g_flag[128];
__device__ int                g_csr[MAXE];
__device__ float              g_mean[MAXN * D];
__device__ __half             g_xh[MAXN * D];  // fp16 copy of x
__device__ __half             g_h1[MAXN * D];  // layer-1 activations (fp16)

// ---------------- small helpers ----------------
__device__ __forceinline__ void acc4h(float& a0, float& a1, float& a2, float& a3,
                                      uint2 v) {
    float2 f0 = __half22float2(*reinterpret_cast<const __half2*>(&v.x));
    float2 f1 = __half22float2(*reinterpret_cast<const __half2*>(&v.y));
    a0 += f0.x; a1 += f0.y; a2 += f1.x; a3 += f1.y;
}
__device__ __forceinline__ void st4h(__half* p, float x, float y, float z, float w) {
    __half2 h0 = __floats2half2_rn(x, y);
    __half2 h1 = __floats2half2_rn(z, w);
    uint2 u;
    u.x = *reinterpret_cast<unsigned*>(&h0);
    u.y = *reinterpret_cast<unsigned*>(&h1);
    *reinterpret_cast<uint2*>(p) = u;
}
__device__ __forceinline__ uint4 pack8h(float4 f0, float4 f1) {
    __half2 h0 = __floats2half2_rn(f0.x, f0.y);
    __half2 h1 = __floats2half2_rn(f0.z, f0.w);
    __half2 h2 = __floats2half2_rn(f1.x, f1.y);
    __half2 h3 = __floats2half2_rn(f1.z, f1.w);
    uint4 u;
    u.x = *reinterpret_cast<unsigned*>(&h0);
    u.y = *reinterpret_cast<unsigned*>(&h1);
    u.z = *reinterpret_cast<unsigned*>(&h2);
    u.w = *reinterpret_cast<unsigned*>(&h3);
    return u;
}
__device__ __forceinline__ uint32_t smem_u32(const void* p) {
    uint32_t a;
    asm("{ .reg .u64 t; cvta.to.shared.u64 t, %1; cvt.u32.u64 %0, t; }"
        : "=r"(a) : "l"(p));
    return a;
}
#define LDSM_X4(r0, r1, r2, r3, addr) \
    asm volatile("ldmatrix.sync.aligned.m8n8.x4.shared.b16 {%0,%1,%2,%3}, [%4];" \
                 : "=r"(r0), "=r"(r1), "=r"(r2), "=r"(r3) : "r"(addr))
__device__ __forceinline__ void mma16816(float* d, uint32_t a0, uint32_t a1,
                                         uint32_t a2, uint32_t a3,
                                         uint32_t b0, uint32_t b1) {
    asm volatile("mma.sync.aligned.m16n8k16.row.col.f32.f16.f16.f32 "
                 "{%0,%1,%2,%3}, {%4,%5,%6,%7}, {%8,%9}, {%0,%1,%2,%3};"
                 : "+f"(d[0]), "+f"(d[1]), "+f"(d[2]), "+f"(d[3])
                 : "r"(a0), "r"(a1), "r"(a2), "r"(a3), "r"(b0), "r"(b1));
}

__device__ __forceinline__ int detect_is64_block(const int* ei32) {
    __shared__ int s_is64;
    if (threadIdx.x == 0) {
        int az = 1;
#pragma unroll
        for (int t = 0; t < 8; t++) az &= (ei32[2 * t + 1] == 0);
        s_is64 = az;
    }
    __syncthreads();
    return s_is64;
}

// ---------------- CSR build ----------------
__global__ void hist_kernel(const void* __restrict__ ei, int* __restrict__ cnt,
                            const float* __restrict__ x, __half* __restrict__ xh,
                            int nquads, int E) {
    const int is64 = detect_is64_block((const int*)ei);
    const int e = blockIdx.x * blockDim.x + threadIdx.x;
    const int stride = gridDim.x * blockDim.x;
    for (int i = e; i < nquads; i += stride) {
        float4 v = reinterpret_cast<const float4*>(x)[i];
        st4h(xh + (size_t)i * 4, v.x, v.y, v.z, v.w);
    }
    if (e >= E) return;
    int d;
    if (is64) d = (int)((const long long*)ei)[(long long)E + e];
    else      d = ((const int*)ei)[(long long)E + e];
    atomicAdd(&cnt[d], 1);
}

__global__ void scan_kernel(const int* __restrict__ cnt, int* __restrict__ ptr,
                            int* __restrict__ cur, unsigned long long* __restrict__ flag,
                            int N, int E) {
    __shared__ int ssum[256];
    const int tid = threadIdx.x;
    const int b = blockIdx.x;
    const int base = b * 1024 + tid * 4;

    int v0 = (base + 0 < N) ? cnt[base + 0] : 0;
    int v1 = (base + 1 < N) ? cnt[base + 1] : 0;
    int v2 = (base + 2 < N) ? cnt[base + 2] : 0;
    int v3 = (base + 3 < N) ? cnt[base + 3] : 0;
    int s = v0 + v1 + v2 + v3;
    ssum[tid] = s;
    __syncthreads();
    for (int st = 1; st < 256; st <<= 1) {
        int t = (tid >= st) ? ssum[tid - st] : 0;
        __syncthreads();
        ssum[tid] += t;
        __syncthreads();
    }
    const int my_incl = ssum[tid];
    const int total = ssum[255];

    if (tid == 0)
        atomicExch(&flag[b], (((unsigned long long)(unsigned)total) << 1) | 1ull);

    int agg = 0;
    if (tid < b) {
        unsigned long long f;
        do { f = atomicAdd(&flag[tid], 0ull); } while (!(f & 1ull));
        agg = (int)(f >> 1);
    }
    __syncthreads();
    ssum[tid] = agg;
    __syncthreads();
    for (int st = 128; st; st >>= 1) {
        if (tid < st) ssum[tid] += ssum[tid + st];
        __syncthreads();
    }
    const int prev = ssum[0];

    int off = prev + my_incl - s;
    if (base + 0 < N) { ptr[base + 0] = off; cur[base + 0] = off; }  off += v0;
    if (base + 1 < N) { ptr[base + 1] = off; cur[base + 1] = off; }  off += v1;
    if (base + 2 < N) { ptr[base + 2] = off; cur[base + 2] = off; }  off += v2;
    if (base + 3 < N) { ptr[base + 3] = off; cur[base + 3] = off; }
    if (b == 0 && tid == 0) ptr[N] = E;
}

__global__ void scatter_kernel(const void* __restrict__ ei, int* __restrict__ cur,
                               int* __restrict__ csr, int* __restrict__ cnt,
                               unsigned long long* __restrict__ flag, int N, int E) {
    const int is64 = detect_is64_block((const int*)ei);
    int e = blockIdx.x * blockDim.x + threadIdx.x;
    if (e < 128) flag[e] = 0ull;
    if (e < N) cnt[e] = 0;
    if (e >= E) return;
    int s, d;
    if (is64) {
        const long long* p = (const long long*)ei;
        s = (int)p[e];
        d = (int)p[(long long)E + e];
    } else {
        const int* p = (const int*)ei;
        s = p[e];
        d = p[(long long)E + e];
    }
    int pos = atomicAdd(&cur[d], 1);
    csr[pos] = s;
}

// ---------------- gather + mean (fp16 rows, fp32 accumulation) ----------------
__global__ void __launch_bounds__(256) gather_mean(
    const __half* __restrict__ feat, const int* __restrict__ ptr,
    const int* __restrict__ csr, float* __restrict__ mean, int N)
{
    const int gid = blockIdx.x * 256 + threadIdx.x;
    const int n = gid >> 4;
    const int q = gid & 15;
    const unsigned gmask = ((threadIdx.x & 31) < 16) ? 0x0000FFFFu : 0xFFFF0000u;

    int rs = 0, re = 0;
    if (n < N) { rs = ptr[n]; re = ptr[n + 1]; }

    float a0 = 0.f, a1 = 0.f, a2 = 0.f, a3 = 0.f;
    const __half* fq = feat + q * 4;

    int b = rs;
    for (; b + 16 <= re; b += 16) {
        int idx = csr[b + q];
#pragma unroll
        for (int h = 0; h < 16; h += 8) {
            int s0 = __shfl_sync(gmask, idx, h + 0, 16);
            int s1 = __shfl_sync(gmask, idx, h + 1, 16);
            int s2 = __shfl_sync(gmask, idx, h + 2, 16);
            int s3 = __shfl_sync(gmask, idx, h + 3, 16);
            int s4 = __shfl_sync(gmask, idx, h + 4, 16);
            int s5 = __shfl_sync(gmask, idx, h + 5, 16);
            int s6 = __shfl_sync(gmask, idx, h + 6, 16);
            int s7 = __shfl_sync(gmask, idx, h + 7, 16);
            uint2 v0 = *(const uint2*)(fq + (size_t)s0 * D);
            uint2 v1 = *(const uint2*)(fq + (size_t)s1 * D);
            uint2 v2 = *(const uint2*)(fq + (size_t)s2 * D);
            uint2 v3 = *(const uint2*)(fq + (size_t)s3 * D);
            uint2 v4 = *(const uint2*)(fq + (size_t)s4 * D);
            uint2 v5 = *(const uint2*)(fq + (size_t)s5 * D);
            uint2 v6 = *(const uint2*)(fq + (size_t)s6 * D);
            uint2 v7 = *(const uint2*)(fq + (size_t)s7 * D);
            acc4h(a0, a1, a2, a3, v0);
            acc4h(a0, a1, a2, a3, v1);
            acc4h(a0, a1, a2, a3, v2);
            acc4h(a0, a1, a2, a3, v3);
            acc4h(a0, a1, a2, a3, v4);
            acc4h(a0, a1, a2, a3, v5);
            acc4h(a0, a1, a2, a3, v6);
            acc4h(a0, a1, a2, a3, v7);
        }
    }
    const int cnt = re - b;
    if (cnt > 0) {
        int idx = (b + q < re) ? csr[b + q] : 0;
#pragma unroll
        for (int j = 0; j < 16; j += 4) {
            if (j < cnt) {
                int s0 = __shfl_sync(gmask, idx, j + 0, 16);
                int s1 = __shfl_sync(gmask, idx, j + 1, 16);
                int s2 = __shfl_sync(gmask, idx, j + 2, 16);
                int s3 = __shfl_sync(gmask, idx, j + 3, 16);
                uint2 v0 = *(const uint2*)(fq + (size_t)s0 * D);
                acc4h(a0, a1, a2, a3, v0);
                if (j + 1 < cnt) {
                    uint2 v1 = *(const uint2*)(fq + (size_t)s1 * D);
                    acc4h(a0, a1, a2, a3, v1);
                }
                if (j + 2 < cnt) {
                    uint2 v2 = *(const uint2*)(fq + (size_t)s2 * D);
                    acc4h(a0, a1, a2, a3, v2);
                }
                if (j + 3 < cnt) {
                    uint2 v3 = *(const uint2*)(fq + (size_t)s3 * D);
                    acc4h(a0, a1, a2, a3, v3);
                }
            }
        }
    }

    if (n < N) {
        const float invd = 1.0f / fmaxf((float)(re - rs), 1.0f);
        float4 r = make_float4(a0 * invd, a1 * invd, a2 * invd, a3 * invd);
        *(float4*)(mean + (size_t)n * D + q * 4) = r;
    }
}

// ---------------- HMMA SAGE transform ----------------
// One 128-node tile per 256-thread CTA (8 warps, 16 rows each).
//   D1[128,64] = [mean | x] (K=128, fp16) @ [Wl ; Wr]^T   via mma.sync m16n8k16
//   h = relu(D1 + bl)   (fp32 accum)
//   !HEAD: store h fp16.  HEAD: D2 = h (K=64) @ Wo^T; out = log_softmax(D2+bo).
// SMEM: A [128 rows x 256B] swizzled 16B chunks (chunk ^= row&7), B [64 x 256B].
template<bool HEAD>
__global__ void __launch_bounds__(256) hmma_transform(
    const float* __restrict__ mean, const __half* __restrict__ xsrc,
    const float* __restrict__ Wl, const float* __restrict__ bl,
    const float* __restrict__ Wr, const float* __restrict__ Wo,
    const float* __restrict__ bo, void* __restrict__ outp, int N)
{
    extern __shared__ char smem[];
    char* SA = smem;                               // 32768 B
    char* SB = smem + 32768;                       // 16384 B
    float* bls = (float*)(smem + 49152);
    float* bos = (float*)(smem + 49408);

    const int tid = threadIdx.x;
    const int w = tid >> 5, lane = tid & 31;
    const int base = blockIdx.x * 128;

    if (tid < 64) { bls[tid] = bl[tid]; if (HEAD) bos[tid] = bo[tid]; }

    // ---- stage A: [mean | x] as 128x128 fp16 (16 chunks/row, swizzled) ----
    for (int i = tid; i < 2048; i += 256) {
        const int row = i >> 4, c = i & 15;
        const int n = base + row;
        uint4 val = make_uint4(0u, 0u, 0u, 0u);
        if (n < N) {
            if (c < 8) {
                float4 f0 = *(const float4*)(mean + (size_t)n * D + c * 8);
                float4 f1 = *(const float4*)(mean + (size_t)n * D + c * 8 + 4);
                val = pack8h(f0, f1);
            } else {
                val = *(const uint4*)(xsrc + (size_t)n * D + (c - 8) * 8);
            }
        }
        *(uint4*)(SA + row * 256 + ((c ^ (row & 7)) << 4)) = val;
    }
    // ---- stage B: [Wl | Wr] as 64x128 fp16 ----
    for (int i = tid; i < 1024; i += 256) {
        const int row = i >> 4, c = i & 15;
        const float* src = (c < 8) ? (Wl + row * D + c * 8)
                                   : (Wr + row * D + (c - 8) * 8);
        float4 f0 = *(const float4*)src;
        float4 f1 = *(const float4*)(src + 4);
        *(uint4*)(SB + row * 256 + ((c ^ (row & 7)) << 4)) = pack8h(f0, f1);
    }
    __syncthreads();

    // ---- MMA 1: per warp rows [16w,16w+16), 8 n-tiles, 8 k-tiles ----
    float acc[8][4];
#pragma unroll
    for (int t = 0; t < 8; t++)
        acc[t][0] = acc[t][1] = acc[t][2] = acc[t][3] = 0.f;

    const int arow = 16 * w + (lane & 15);
    const int ac = lane >> 4;                      // 0/1: k-chunk half
    const int bn = (lane & 7) + ((lane >> 4) << 3);
    const int bc = (lane >> 3) & 1;

#pragma unroll
    for (int t = 0; t < 8; t++) {
        uint32_t a0, a1, a2, a3;
        uint32_t aaddr = smem_u32(SA + arow * 256 + (((2 * t + ac) ^ (arow & 7)) << 4));
        LDSM_X4(a0, a1, a2, a3, aaddr);
#pragma unroll
        for (int p = 0; p < 4; p++) {
            const int nn = bn + 16 * p;
            uint32_t baddr = smem_u32(SB + nn * 256 + (((2 * t + bc) ^ (nn & 7)) << 4));
            uint32_t b0, b1, b2, b3;
            LDSM_X4(b0, b1, b2, b3, baddr);
            mma16816(acc[2 * p + 0], a0, a1, a2, a3, b0, b1);
            mma16816(acc[2 * p + 1], a0, a1, a2, a3, b2, b3);
        }
    }
    __syncthreads();                               // A/B consumed

    // ---- epilogue 1: bias + relu (fragment layout) ----
    const int r0 = 16 * w + (lane >> 2);
    const int r1 = r0 + 8;
    const int cb = 2 * (lane & 3);
#pragma unroll
    for (int t = 0; t < 8; t++) {
        const int c = 8 * t + cb;
        acc[t][0] = fmaxf(acc[t][0] + bls[c],     0.f);
        acc[t][1] = fmaxf(acc[t][1] + bls[c + 1], 0.f);
        acc[t][2] = fmaxf(acc[t][2] + bls[c],     0.f);
        acc[t][3] = fmaxf(acc[t][3] + bls[c + 1], 0.f);
    }

    if (!HEAD) {
        // stage h (fp16) at SA, row stride 144B (16B-aligned, conflict-free)
#pragma unroll
        for (int t = 0; t < 8; t++) {
            const int c = 8 * t + cb;
            *(__half2*)(SA + r0 * 144 + c * 2) = __floats2half2_rn(acc[t][0], acc[t][1]);
            *(__half2*)(SA + r1 * 144 + c * 2) = __floats2half2_rn(acc[t][2], acc[t][3]);
        }
        __syncthreads();
        for (int i = tid; i < 1024; i += 256) {
            const int row = i >> 3, c8 = i & 7;
            if (base + row < N)
                *(uint4*)((__half*)outp + (size_t)(base + row) * D + c8 * 8) =
                    *(uint4*)(SA + row * 144 + c8 * 16);
        }
    } else {
        // stage h (fp16) swizzled at SA: 128 rows x 128B (8 chunks)
#pragma unroll
        for (int t = 0; t < 8; t++) {
            *(__half2*)(SA + r0 * 128 + ((t ^ (r0 & 7)) << 4) + cb * 2) =
                __floats2half2_rn(acc[t][0], acc[t][1]);
            *(__half2*)(SA + r1 * 128 + ((t ^ (r1 & 7)) << 4) + cb * 2) =
                __floats2half2_rn(acc[t][2], acc[t][3]);
        }
        // stage Wo at SB: 64 rows x 128B
        for (int i = tid; i < 512; i += 256) {
            const int row = i >> 3, c = i & 7;
            float4 f0 = *(const float4*)(Wo + row * D + c * 8);
            float4 f1 = *(const float4*)(Wo + row * D + c * 8 + 4);
            *(uint4*)(SB + row * 128 + ((c ^ (row & 7)) << 4)) = pack8h(f0, f1);
        }
        __syncthreads();

        // ---- MMA 2: K=64, 4 k-tiles ----
        float ac2[8][4];
#pragma unroll
        for (int t = 0; t < 8; t++)
            ac2[t][0] = ac2[t][1] = ac2[t][2] = ac2[t][3] = 0.f;
#pragma unroll
        for (int t = 0; t < 4; t++) {
            uint32_t a0, a1, a2, a3;
            uint32_t aaddr = smem_u32(SA + arow * 128 + (((2 * t + ac) ^ (arow & 7)) << 4));
            LDSM_X4(a0, a1, a2, a3, aaddr);
#pragma unroll
            for (int p = 0; p < 4; p++) {
                const int nn = bn + 16 * p;
                uint32_t baddr = smem_u32(SB + nn * 128 + (((2 * t + bc) ^ (nn & 7)) << 4));
                uint32_t b0, b1, b2, b3;
                LDSM_X4(b0, b1, b2, b3, baddr);
                mma16816(ac2[2 * p + 0], a0, a1, a2, a3, b0, b1);
                mma16816(ac2[2 * p + 1], a0, a1, a2, a3, b2, b3);
            }
        }
        __syncthreads();                           // SA/SB consumed

        // ---- stage logits fp32 at smem base, row stride 264B (66 floats) ----
#pragma unroll
        for (int t = 0; t < 8; t++) {
            const int c = 8 * t + cb;
            *(float2*)(smem + r0 * 264 + c * 4) =
                make_float2(ac2[t][0] + bos[c], ac2[t][1] + bos[c + 1]);
            *(float2*)(smem + r1 * 264 + c * 4) =
                make_float2(ac2[t][2] + bos[c], ac2[t][3] + bos[c + 1]);
        }
        __syncthreads();

        // ---- per-row log_softmax (128 threads, one row each) ----
        if (tid < 128) {
            const float* lr = (const float*)(smem + tid * 264);
            float mx = -1e30f;
#pragma unroll
            for (int c = 0; c < 64; c++) mx = fmaxf(mx, lr[c]);
            float sm = 0.f;
#pragma unroll
            for (int c = 0; c < 64; c++) sm += expf(lr[c] - mx);
            const float lse = mx + logf(sm);
            const int n = base + tid;
            if (n < N) {
                float* op = (float*)outp + (size_t)n * D;
#pragma unroll
                for (int c = 0; c < 64; c += 4) {
                    float4 r = make_float4(lr[c] - lse, lr[c + 1] - lse,
                                           lr[c + 2] - lse, lr[c + 3] - lse);
                    *(float4*)(op + c) = r;
                }
            }
        }
    }
}

// ---------------------------------------------------------------------------
extern "C" void kernel_launch(void* const* d_in, const int* in_sizes, int n_in,
                              void* d_out, int out_size) {
    const float* x    = (const float*)d_in[0];
    const void*  ei   = d_in[1];
    const float* W1l  = (const float*)d_in[2];
    const float* b1l  = (const float*)d_in[3];
    const float* W1r  = (const float*)d_in[4];
    const float* W2l  = (const float*)d_in[5];
    const float* b2l  = (const float*)d_in[6];
    const float* W2r  = (const float*)d_in[7];
    const float* Wout = (const float*)d_in[8];
    const float* bout = (const float*)d_in[9];

    const int N = in_sizes[0] / D;
    const int E = in_sizes[1] / 2;

    int*   cnt;  cudaGetSymbolAddress((void**)&cnt,  g_cnt);
    int*   ptr;  cudaGetSymbolAddress((void**)&ptr,  g_ptr);
    int*   cur;  cudaGetSymbolAddress((void**)&cur,  g_cur);
    unsigned long long* flag; cudaGetSymbolAddress((void**)&flag, g_flag);
    int*   csr;  cudaGetSymbolAddress((void**)&csr,  g_csr);
    float* mean; cudaGetSymbolAddress((void**)&mean, g_mean);
    __half* xh;  cudaGetSymbolAddress((void**)&xh,   g_xh);
    __half* h1;  cudaGetSymbolAddress((void**)&h1,   g_h1);

    const int SMEM_MMA = 49152 + 512;              // A+B + two bias arrays

    cudaStreamCaptureStatus cs = cudaStreamCaptureStatusNone;
    cudaStreamIsCapturing(0, &cs);
    if (cs == cudaStreamCaptureStatusNone) {
        cudaFuncSetAttribute(hmma_transform<false>,
                             cudaFuncAttributeMaxDynamicSharedMemorySize, SMEM_MMA);
        cudaFuncSetAttribute(hmma_transform<true>,
                             cudaFuncAttributeMaxDynamicSharedMemorySize, SMEM_MMA);
    }

    const int nb = (N + 1023) / 1024;
    const int eblocks = (E + 255) / 256;
    const int gblocks = (N * 16 + 255) / 256;
    const int mblocks = (N + 127) / 128;           // 782 tiles

    // CSR build: [0] hist + x->fp16, [1] scan, [2] scatter(+state reset)
    hist_kernel<<<eblocks, 256>>>(ei, cnt, x, xh, N * D / 4, E);
    scan_kernel<<<nb, 256>>>(cnt, ptr, cur, flag, N, E);
    scatter_kernel<<<eblocks, 256>>>(ei, cur, csr, cnt, flag, N, E);

    // Layer 1: [3] gather (profiled), [4] HMMA transform -> fp16 h1
    gather_mean<<<gblocks, 256>>>(xh, ptr, csr, mean, N);
    hmma_transform<false><<<mblocks, 256, SMEM_MMA>>>(
        mean, xh, W1l, b1l, W1r, nullptr, nullptr, h1, N);
    // Layer 2 + head: [5] gather, [6] HMMA transform + head + log_softmax
    gather_mean<<<gblocks, 256>>>(h1, ptr, csr, mean, N);
    hmma_transform<true><<<mblocks, 256, SMEM_MMA>>>(
        mean, h1, W2l, b2l, W2r, Wout, bout, (float*)d_out, N);
}

// round 9
// speedup vs baseline: 4.1282x; 1.0604x over previous
#include <cuda_runtime.h>
#include <cuda_fp16.h>
#include <math.h>
#include <stdint.h>

// GraphSAGE encoder:
//   CSR build (3 launches) -> fp16 gather/mean (pairwise HADD2 pre-reduce,
//   fp16 mean) -> HMMA (mma.sync m16n8k16) transform
//   (layer 2 fuses output head GEMM + log_softmax).
// NOTE: tcgen05 unusable — harness ptxas targets sm_103 (no 'a').
// N=100000, E=1600000, D=64.
// State invariant: g_cnt and g_flag are zero at entry to each kernel_launch
// (zero-init at load; scatter_kernel re-zeroes them for the next replay).

#define MAXN 100000
#define MAXE 1600000
#define D 64

__device__ int                g_cnt[MAXN];
__device__ int                g_ptr[MAXN + 1];
__device__ int                g_cur[MAXN];
__device__ unsigned long long g_flag[128];
__device__ int                g_csr[MAXE];
__device__ __half             g_mean[MAXN * D]; // fp16 mean (gather output)
__device__ __half             g_xh[MAXN * D];   // fp16 copy of x
__device__ __half             g_h1[MAXN * D];   // layer-1 activations (fp16)

// ---------------- small helpers ----------------
__device__ __forceinline__ void acc4h(float& a0, float& a1, float& a2, float& a3,
                                      uint2 v) {
    float2 f0 = __half22float2(*reinterpret_cast<const __half2*>(&v.x));
    float2 f1 = __half22float2(*reinterpret_cast<const __half2*>(&v.y));
    a0 += f0.x; a1 += f0.y; a2 += f1.x; a3 += f1.y;
}
// pairwise: fp16 add two neighbor rows, then fp32 accumulate
__device__ __forceinline__ void accp(float& a0, float& a1, float& a2, float& a3,
                                     uint2 u, uint2 v) {
    __half2 s0 = __hadd2(*reinterpret_cast<const __half2*>(&u.x),
                         *reinterpret_cast<const __half2*>(&v.x));
    __half2 s1 = __hadd2(*reinterpret_cast<const __half2*>(&u.y),
                         *reinterpret_cast<const __half2*>(&v.y));
    float2 f0 = __half22float2(s0);
    float2 f1 = __half22float2(s1);
    a0 += f0.x; a1 += f0.y; a2 += f1.x; a3 += f1.y;
}
__device__ __forceinline__ void st4h(__half* p, float x, float y, float z, float w) {
    __half2 h0 = __floats2half2_rn(x, y);
    __half2 h1 = __floats2half2_rn(z, w);
    uint2 u;
    u.x = *reinterpret_cast<unsigned*>(&h0);
    u.y = *reinterpret_cast<unsigned*>(&h1);
    *reinterpret_cast<uint2*>(p) = u;
}
__device__ __forceinline__ uint4 pack8h(float4 f0, float4 f1) {
    __half2 h0 = __floats2half2_rn(f0.x, f0.y);
    __half2 h1 = __floats2half2_rn(f0.z, f0.w);
    __half2 h2 = __floats2half2_rn(f1.x, f1.y);
    __half2 h3 = __floats2half2_rn(f1.z, f1.w);
    uint4 u;
    u.x = *reinterpret_cast<unsigned*>(&h0);
    u.y = *reinterpret_cast<unsigned*>(&h1);
    u.z = *reinterpret_cast<unsigned*>(&h2);
    u.w = *reinterpret_cast<unsigned*>(&h3);
    return u;
}
__device__ __forceinline__ uint32_t smem_u32(const void* p) {
    uint32_t a;
    asm("{ .reg .u64 t; cvta.to.shared.u64 t, %1; cvt.u32.u64 %0, t; }"
        : "=r"(a) : "l"(p));
    return a;
}
#define LDSM_X4(r0, r1, r2, r3, addr) \
    asm volatile("ldmatrix.sync.aligned.m8n8.x4.shared.b16 {%0,%1,%2,%3}, [%4];" \
                 : "=r"(r0), "=r"(r1), "=r"(r2), "=r"(r3) : "r"(addr))
__device__ __forceinline__ void mma16816(float* d, uint32_t a0, uint32_t a1,
                                         uint32_t a2, uint32_t a3,
                                         uint32_t b0, uint32_t b1) {
    asm volatile("mma.sync.aligned.m16n8k16.row.col.f32.f16.f16.f32 "
                 "{%0,%1,%2,%3}, {%4,%5,%6,%7}, {%8,%9}, {%0,%1,%2,%3};"
                 : "+f"(d[0]), "+f"(d[1]), "+f"(d[2]), "+f"(d[3])
                 : "r"(a0), "r"(a1), "r"(a2), "r"(a3), "r"(b0), "r"(b1));
}

__device__ __forceinline__ int detect_is64_block(const int* ei32) {
    __shared__ int s_is64;
    if (threadIdx.x == 0) {
        int az = 1;
#pragma unroll
        for (int t = 0; t < 8; t++) az &= (ei32[2 * t + 1] == 0);
        s_is64 = az;
    }
    __syncthreads();
    return s_is64;
}

// ---------------- CSR build ----------------
__global__ void hist_kernel(const void* __restrict__ ei, int* __restrict__ cnt,
                            const float* __restrict__ x, __half* __restrict__ xh,
                            int nquads, int E) {
    const int is64 = detect_is64_block((const int*)ei);
    const int e = blockIdx.x * blockDim.x + threadIdx.x;
    const int stride = gridDim.x * blockDim.x;
    for (int i = e; i < nquads; i += stride) {
        float4 v = reinterpret_cast<const float4*>(x)[i];
        st4h(xh + (size_t)i * 4, v.x, v.y, v.z, v.w);
    }
    if (e >= E) return;
    int d;
    if (is64) d = (int)((const long long*)ei)[(long long)E + e];
    else      d = ((const int*)ei)[(long long)E + e];
    atomicAdd(&cnt[d], 1);
}

__global__ void scan_kernel(const int* __restrict__ cnt, int* __restrict__ ptr,
                            int* __restrict__ cur, unsigned long long* __restrict__ flag,
                            int N, int E) {
    __shared__ int ssum[256];
    const int tid = threadIdx.x;
    const int b = blockIdx.x;
    const int base = b * 1024 + tid * 4;

    int v0 = (base + 0 < N) ? cnt[base + 0] : 0;
    int v1 = (base + 1 < N) ? cnt[base + 1] : 0;
    int v2 = (base + 2 < N) ? cnt[base + 2] : 0;
    int v3 = (base + 3 < N) ? cnt[base + 3] : 0;
    int s = v0 + v1 + v2 + v3;
    ssum[tid] = s;
    __syncthreads();
    for (int st = 1; st < 256; st <<= 1) {
        int t = (tid >= st) ? ssum[tid - st] : 0;
        __syncthreads();
        ssum[tid] += t;
        __syncthreads();
    }
    const int my_incl = ssum[tid];
    const int total = ssum[255];

    if (tid == 0)
        atomicExch(&flag[b], (((unsigned long long)(unsigned)total) << 1) | 1ull);

    int agg = 0;
    if (tid < b) {
        unsigned long long f;
        do { f = atomicAdd(&flag[tid], 0ull); } while (!(f & 1ull));
        agg = (int)(f >> 1);
    }
    __syncthreads();
    ssum[tid] = agg;
    __syncthreads();
    for (int st = 128; st; st >>= 1) {
        if (tid < st) ssum[tid] += ssum[tid + st];
        __syncthreads();
    }
    const int prev = ssum[0];

    int off = prev + my_incl - s;
    if (base + 0 < N) { ptr[base + 0] = off; cur[base + 0] = off; }  off += v0;
    if (base + 1 < N) { ptr[base + 1] = off; cur[base + 1] = off; }  off += v1;
    if (base + 2 < N) { ptr[base + 2] = off; cur[base + 2] = off; }  off += v2;
    if (base + 3 < N) { ptr[base + 3] = off; cur[base + 3] = off; }
    if (b == 0 && tid == 0) ptr[N] = E;
}

__global__ void scatter_kernel(const void* __restrict__ ei, int* __restrict__ cur,
                               int* __restrict__ csr, int* __restrict__ cnt,
                               unsigned long long* __restrict__ flag, int N, int E) {
    const int is64 = detect_is64_block((const int*)ei);
    int e = blockIdx.x * blockDim.x + threadIdx.x;
    if (e < 128) flag[e] = 0ull;
    if (e < N) cnt[e] = 0;
    if (e >= E) return;
    int s, d;
    if (is64) {
        const long long* p = (const long long*)ei;
        s = (int)p[e];
        d = (int)p[(long long)E + e];
    } else {
        const int* p = (const int*)ei;
        s = p[e];
        d = p[(long long)E + e];
    }
    int pos = atomicAdd(&cur[d], 1);
    csr[pos] = s;
}

// ---------------- gather + mean (fp16 rows, pairwise HADD2, fp16 out) --------
__global__ void __launch_bounds__(256) gather_mean(
    const __half* __restrict__ feat, const int* __restrict__ ptr,
    const int* __restrict__ csr, __half* __restrict__ mean, int N)
{
    const int gid = blockIdx.x * 256 + threadIdx.x;
    const int n = gid >> 4;
    const int q = gid & 15;
    const unsigned gmask = ((threadIdx.x & 31) < 16) ? 0x0000FFFFu : 0xFFFF0000u;

    int rs = 0, re = 0;
    if (n < N) { rs = ptr[n]; re = ptr[n + 1]; }

    float a0 = 0.f, a1 = 0.f, a2 = 0.f, a3 = 0.f;
    const __half* fq = feat + q * 4;

    int b = rs;
    for (; b + 16 <= re; b += 16) {
        int idx = csr[b + q];
#pragma unroll
        for (int h = 0; h < 16; h += 8) {
            int s0 = __shfl_sync(gmask, idx, h + 0, 16);
            int s1 = __shfl_sync(gmask, idx, h + 1, 16);
            int s2 = __shfl_sync(gmask, idx, h + 2, 16);
            int s3 = __shfl_sync(gmask, idx, h + 3, 16);
            int s4 = __shfl_sync(gmask, idx, h + 4, 16);
            int s5 = __shfl_sync(gmask, idx, h + 5, 16);
            int s6 = __shfl_sync(gmask, idx, h + 6, 16);
            int s7 = __shfl_sync(gmask, idx, h + 7, 16);
            uint2 v0 = *(const uint2*)(fq + (size_t)s0 * D);
            uint2 v1 = *(const uint2*)(fq + (size_t)s1 * D);
            uint2 v2 = *(const uint2*)(fq + (size_t)s2 * D);
            uint2 v3 = *(const uint2*)(fq + (size_t)s3 * D);
            uint2 v4 = *(const uint2*)(fq + (size_t)s4 * D);
            uint2 v5 = *(const uint2*)(fq + (size_t)s5 * D);
            uint2 v6 = *(const uint2*)(fq + (size_t)s6 * D);
            uint2 v7 = *(const uint2*)(fq + (size_t)s7 * D);
            accp(a0, a1, a2, a3, v0, v1);
            accp(a0, a1, a2, a3, v2, v3);
            accp(a0, a1, a2, a3, v4, v5);
            accp(a0, a1, a2, a3, v6, v7);
        }
    }
    const int cnt = re - b;
    if (cnt > 0) {
        int idx = (b + q < re) ? csr[b + q] : 0;
#pragma unroll
        for (int j = 0; j < 16; j += 4) {
            if (j < cnt) {
                int s0 = __shfl_sync(gmask, idx, j + 0, 16);
                int s1 = __shfl_sync(gmask, idx, j + 1, 16);
                int s2 = __shfl_sync(gmask, idx, j + 2, 16);
                int s3 = __shfl_sync(gmask, idx, j + 3, 16);
                uint2 v0 = *(const uint2*)(fq + (size_t)s0 * D);
                acc4h(a0, a1, a2, a3, v0);
                if (j + 1 < cnt) {
                    uint2 v1 = *(const uint2*)(fq + (size_t)s1 * D);
                    acc4h(a0, a1, a2, a3, v1);
                }
                if (j + 2 < cnt) {
                    uint2 v2 = *(const uint2*)(fq + (size_t)s2 * D);
                    acc4h(a0, a1, a2, a3, v2);
                }
                if (j + 3 < cnt) {
                    uint2 v3 = *(const uint2*)(fq + (size_t)s3 * D);
                    acc4h(a0, a1, a2, a3, v3);
                }
            }
        }
    }

    if (n < N) {
        const float invd = 1.0f / fmaxf((float)(re - rs), 1.0f);
        st4h(mean + (size_t)n * D + q * 4,
             a0 * invd, a1 * invd, a2 * invd, a3 * invd);
    }
}

// ---------------- HMMA SAGE transform ----------------
// One 128-node tile per 256-thread CTA (8 warps, 16 rows each).
//   D1[128,64] = [mean | x] (K=128, fp16) @ [Wl ; Wr]^T   via mma.sync m16n8k16
//   h = relu(D1 + bl)   (fp32 accum)
//   !HEAD: store h fp16.  HEAD: D2 = h (K=64) @ Wo^T; out = log_softmax(D2+bo).
// SMEM: A [128 rows x 256B] swizzled 16B chunks (chunk ^= row&7), B [64 x 256B].
template<bool HEAD>
__global__ void __launch_bounds__(256) hmma_transform(
    const __half* __restrict__ mean, const __half* __restrict__ xsrc,
    const float* __restrict__ Wl, const float* __restrict__ bl,
    const float* __restrict__ Wr, const float* __restrict__ Wo,
    const float* __restrict__ bo, void* __restrict__ outp, int N)
{
    extern __shared__ char smem[];
    char* SA = smem;                               // 32768 B
    char* SB = smem + 32768;                       // 16384 B
    float* bls = (float*)(smem + 49152);
    float* bos = (float*)(smem + 49408);

    const int tid = threadIdx.x;
    const int w = tid >> 5, lane = tid & 31;
    const int base = blockIdx.x * 128;

    if (tid < 64) { bls[tid] = bl[tid]; if (HEAD) bos[tid] = bo[tid]; }

    // ---- stage A: [mean | x] as 128x128 fp16 (pure uint4 copies) ----
    for (int i = tid; i < 2048; i += 256) {
        const int row = i >> 4, c = i & 15;
        const int n = base + row;
        uint4 val = make_uint4(0u, 0u, 0u, 0u);
        if (n < N) {
            val = (c < 8) ? *(const uint4*)(mean + (size_t)n * D + c * 8)
                          : *(const uint4*)(xsrc + (size_t)n * D + (c - 8) * 8);
        }
        *(uint4*)(SA + row * 256 + ((c ^ (row & 7)) << 4)) = val;
    }
    // ---- stage B: [Wl | Wr] as 64x128 fp16 ----
    for (int i = tid; i < 1024; i += 256) {
        const int row = i >> 4, c = i & 15;
        const float* src = (c < 8) ? (Wl + row * D + c * 8)
                                   : (Wr + row * D + (c - 8) * 8);
        float4 f0 = *(const float4*)src;
        float4 f1 = *(const float4*)(src + 4);
        *(uint4*)(SB + row * 256 + ((c ^ (row & 7)) << 4)) = pack8h(f0, f1);
    }
    __syncthreads();

    // ---- MMA 1: per warp rows [16w,16w+16), 8 n-tiles, 8 k-tiles ----
    float acc[8][4];
#pragma unroll
    for (int t = 0; t < 8; t++)
        acc[t][0] = acc[t][1] = acc[t][2] = acc[t][3] = 0.f;

    const int arow = 16 * w + (lane & 15);
    const int ac = lane >> 4;                      // 0/1: k-chunk half
    const int bn = (lane & 7) + ((lane >> 4) << 3);
    const int bc = (lane >> 3) & 1;

#pragma unroll
    for (int t = 0; t < 8; t++) {
        uint32_t a0, a1, a2, a3;
        uint32_t aaddr = smem_u32(SA + arow * 256 + (((2 * t + ac) ^ (arow & 7)) << 4));
        LDSM_X4(a0, a1, a2, a3, aaddr);
#pragma unroll
        for (int p = 0; p < 4; p++) {
            const int nn = bn + 16 * p;
            uint32_t baddr = smem_u32(SB + nn * 256 + (((2 * t + bc) ^ (nn & 7)) << 4));
            uint32_t b0, b1, b2, b3;
            LDSM_X4(b0, b1, b2, b3, baddr);
            mma16816(acc[2 * p + 0], a0, a1, a2, a3, b0, b1);
            mma16816(acc[2 * p + 1], a0, a1, a2, a3, b2, b3);
        }
    }
    __syncthreads();                               // A/B consumed

    // ---- epilogue 1: bias + relu (fragment layout) ----
    const int r0 = 16 * w + (lane >> 2);
    const int r1 = r0 + 8;
    const int cb = 2 * (lane & 3);
#pragma unroll
    for (int t = 0; t < 8; t++) {
        const int c = 8 * t + cb;
        acc[t][0] = fmaxf(acc[t][0] + bls[c],     0.f);
        acc[t][1] = fmaxf(acc[t][1] + bls[c + 1], 0.f);
        acc[t][2] = fmaxf(acc[t][2] + bls[c],     0.f);
        acc[t][3] = fmaxf(acc[t][3] + bls[c + 1], 0.f);
    }

    if (!HEAD) {
        // stage h (fp16) at SA, row stride 144B (16B-aligned, conflict-free)
#pragma unroll
        for (int t = 0; t < 8; t++) {
            const int c = 8 * t + cb;
            *(__half2*)(SA + r0 * 144 + c * 2) = __floats2half2_rn(acc[t][0], acc[t][1]);
            *(__half2*)(SA + r1 * 144 + c * 2) = __floats2half2_rn(acc[t][2], acc[t][3]);
        }
        __syncthreads();
        for (int i = tid; i < 1024; i += 256) {
            const int row = i >> 3, c8 = i & 7;
            if (base + row < N)
                *(uint4*)((__half*)outp + (size_t)(base + row) * D + c8 * 8) =
                    *(uint4*)(SA + row * 144 + c8 * 16);
        }
    } else {
        // stage h (fp16) swizzled at SA: 128 rows x 128B (8 chunks)
#pragma unroll
        for (int t = 0; t < 8; t++) {
            *(__half2*)(SA + r0 * 128 + ((t ^ (r0 & 7)) << 4) + cb * 2) =
                __floats2half2_rn(acc[t][0], acc[t][1]);
            *(__half2*)(SA + r1 * 128 + ((t ^ (r1 & 7)) << 4) + cb * 2) =
                __floats2half2_rn(acc[t][2], acc[t][3]);
        }
        // stage Wo at SB: 64 rows x 128B
        for (int i = tid; i < 512; i += 256) {
            const int row = i >> 3, c = i & 7;
            float4 f0 = *(const float4*)(Wo + row * D + c * 8);
            float4 f1 = *(const float4*)(Wo + row * D + c * 8 + 4);
            *(uint4*)(SB + row * 128 + ((c ^ (row & 7)) << 4)) = pack8h(f0, f1);
        }
        __syncthreads();

        // ---- MMA 2: K=64, 4 k-tiles ----
        float ac2[8][4];
#pragma unroll
        for (int t = 0; t < 8; t++)
            ac2[t][0] = ac2[t][1] = ac2[t][2] = ac2[t][3] = 0.f;
#pragma unroll
        for (int t = 0; t < 4; t++) {
            uint32_t a0, a1, a2, a3;
            uint32_t aaddr = smem_u32(SA + arow * 128 + (((2 * t + ac) ^ (arow & 7)) << 4));
            LDSM_X4(a0, a1, a2, a3, aaddr);
#pragma unroll
            for (int p = 0; p < 4; p++) {
                const int nn = bn + 16 * p;
                uint32_t baddr = smem_u32(SB + nn * 128 + (((2 * t + bc) ^ (nn & 7)) << 4));
                uint32_t b0, b1, b2, b3;
                LDSM_X4(b0, b1, b2, b3, baddr);
                mma16816(ac2[2 * p + 0], a0, a1, a2, a3, b0, b1);
                mma16816(ac2[2 * p + 1], a0, a1, a2, a3, b2, b3);
            }
        }
        __syncthreads();                           // SA/SB consumed

        // ---- stage logits fp32 at smem base, row stride 264B (66 floats) ----
#pragma unroll
        for (int t = 0; t < 8; t++) {
            const int c = 8 * t + cb;
            *(float2*)(smem + r0 * 264 + c * 4) =
                make_float2(ac2[t][0] + bos[c], ac2[t][1] + bos[c + 1]);
            *(float2*)(smem + r1 * 264 + c * 4) =
                make_float2(ac2[t][2] + bos[c], ac2[t][3] + bos[c + 1]);
        }
        __syncthreads();

        // ---- per-row log_softmax (128 threads, one row each) ----
        if (tid < 128) {
            const float* lr = (const float*)(smem + tid * 264);
            float mx = -1e30f;
#pragma unroll
            for (int c = 0; c < 64; c++) mx = fmaxf(mx, lr[c]);
            float sm = 0.f;
#pragma unroll
            for (int c = 0; c < 64; c++) sm += expf(lr[c] - mx);
            const float lse = mx + logf(sm);
            const int n = base + tid;
            if (n < N) {
                float* op = (float*)outp + (size_t)n * D;
#pragma unroll
                for (int c = 0; c < 64; c += 4) {
                    float4 r = make_float4(lr[c] - lse, lr[c + 1] - lse,
                                           lr[c + 2] - lse, lr[c + 3] - lse);
                    *(float4*)(op + c) = r;
                }
            }
        }
    }
}

// ---------------------------------------------------------------------------
extern "C" void kernel_launch(void* const* d_in, const int* in_sizes, int n_in,
                              void* d_out, int out_size) {
    const float* x    = (const float*)d_in[0];
    const void*  ei   = d_in[1];
    const float* W1l  = (const float*)d_in[2];
    const float* b1l  = (const float*)d_in[3];
    const float* W1r  = (const float*)d_in[4];
    const float* W2l  = (const float*)d_in[5];
    const float* b2l  = (const float*)d_in[6];
    const float* W2r  = (const float*)d_in[7];
    const float* Wout = (const float*)d_in[8];
    const float* bout = (const float*)d_in[9];

    const int N = in_sizes[0] / D;
    const int E = in_sizes[1] / 2;

    int*   cnt;  cudaGetSymbolAddress((void**)&cnt,  g_cnt);
    int*   ptr;  cudaGetSymbolAddress((void**)&ptr,  g_ptr);
    int*   cur;  cudaGetSymbolAddress((void**)&cur,  g_cur);
    unsigned long long* flag; cudaGetSymbolAddress((void**)&flag, g_flag);
    int*   csr;  cudaGetSymbolAddress((void**)&csr,  g_csr);
    __half* mean; cudaGetSymbolAddress((void**)&mean, g_mean);
    __half* xh;  cudaGetSymbolAddress((void**)&xh,   g_xh);
    __half* h1;  cudaGetSymbolAddress((void**)&h1,   g_h1);

    const int SMEM_MMA = 49152 + 512;              // A+B + two bias arrays

    cudaStreamCaptureStatus cs = cudaStreamCaptureStatusNone;
    cudaStreamIsCapturing(0, &cs);
    if (cs == cudaStreamCaptureStatusNone) {
        cudaFuncSetAttribute(hmma_transform<false>,
                             cudaFuncAttributeMaxDynamicSharedMemorySize, SMEM_MMA);
        cudaFuncSetAttribute(hmma_transform<true>,
                             cudaFuncAttributeMaxDynamicSharedMemorySize, SMEM_MMA);
    }

    const int nb = (N + 1023) / 1024;
    const int eblocks = (E + 255) / 256;
    const int gblocks = (N * 16 + 255) / 256;
    const int mblocks = (N + 127) / 128;           // 782 tiles

    // CSR build: [0] hist + x->fp16, [1] scan, [2] scatter(+state reset)
    hist_kernel<<<eblocks, 256>>>(ei, cnt, x, xh, N * D / 4, E);
    scan_kernel<<<nb, 256>>>(cnt, ptr, cur, flag, N, E);
    scatter_kernel<<<eblocks, 256>>>(ei, cur, csr, cnt, flag, N, E);

    // Layer 1: [3] gather (profiled), [4] HMMA transform -> fp16 h1
    gather_mean<<<gblocks, 256>>>(xh, ptr, csr, mean, N);
    hmma_transform<false><<<mblocks, 256, SMEM_MMA>>>(
        mean, xh, W1l, b1l, W1r, nullptr, nullptr, h1, N);
    // Layer 2 + head: [5] gather, [6] HMMA transform + head + log_softmax
    gather_mean<<<gblocks, 256>>>(h1, ptr, csr, mean, N);
    hmma_transform<true><<<mblocks, 256, SMEM_MMA>>>(
        mean, h1, W2l, b2l, W2r, Wout, bout, (float*)d_out, N);
}

// round 10
// speedup vs baseline: 4.2552x; 1.0308x over previous
#include <cuda_runtime.h>
#include <cuda_fp16.h>
#include <math.h>
#include <stdint.h>

// GraphSAGE encoder:
//   CSR build (3 launches, 4 edges/thread) -> fp16 gather/mean (full fp16
//   accumulation, branch-free zero-row tail) -> HMMA transform
//   (layer 2 fuses output head GEMM + log_softmax).
// NOTE: tcgen05 unusable — harness ptxas targets sm_103 (no 'a').
// N=100000, E=1600000, D=64.
// State invariant: g_cnt and g_flag are zero at entry to each kernel_launch
// (zero-init at load; scatter_kernel re-zeroes them for the next replay).

#define MAXN 100000
#define MAXE 1600000
#define D 64

__device__ int                g_cnt[MAXN];
__device__ int                g_ptr[MAXN + 1];
__device__ int                g_cur[MAXN];
__device__ unsigned long long g_flag[128];
__device__ int                g_csr[MAXE];
__device__ __half             g_mean[MAXN * D]; // fp16 mean (gather output)
__device__ __half             g_xh[MAXN * D];   // fp16 copy of x
__device__ __half             g_h1[MAXN * D];   // layer-1 activations (fp16)
__device__ __align__(16) __half g_zero[64];     // stays zero (never written)

// ---------------- small helpers ----------------
__device__ __forceinline__ void st4h(__half* p, float x, float y, float z, float w) {
    __half2 h0 = __floats2half2_rn(x, y);
    __half2 h1 = __floats2half2_rn(z, w);
    uint2 u;
    u.x = *reinterpret_cast<unsigned*>(&h0);
    u.y = *reinterpret_cast<unsigned*>(&h1);
    *reinterpret_cast<uint2*>(p) = u;
}
__device__ __forceinline__ uint4 pack8h(float4 f0, float4 f1) {
    __half2 h0 = __floats2half2_rn(f0.x, f0.y);
    __half2 h1 = __floats2half2_rn(f0.z, f0.w);
    __half2 h2 = __floats2half2_rn(f1.x, f1.y);
    __half2 h3 = __floats2half2_rn(f1.z, f1.w);
    uint4 u;
    u.x = *reinterpret_cast<unsigned*>(&h0);
    u.y = *reinterpret_cast<unsigned*>(&h1);
    u.z = *reinterpret_cast<unsigned*>(&h2);
    u.w = *reinterpret_cast<unsigned*>(&h3);
    return u;
}
__device__ __forceinline__ __half2 u2h2(unsigned v) {
    return *reinterpret_cast<const __half2*>(&v);
}
__device__ __forceinline__ uint32_t smem_u32(const void* p) {
    uint32_t a;
    asm("{ .reg .u64 t; cvta.to.shared.u64 t, %1; cvt.u32.u64 %0, t; }"
        : "=r"(a) : "l"(p));
    return a;
}
#define LDSM_X4(r0, r1, r2, r3, addr) \
    asm volatile("ldmatrix.sync.aligned.m8n8.x4.shared.b16 {%0,%1,%2,%3}, [%4];" \
                 : "=r"(r0), "=r"(r1), "=r"(r2), "=r"(r3) : "r"(addr))
__device__ __forceinline__ void mma16816(float* d, uint32_t a0, uint32_t a1,
                                         uint32_t a2, uint32_t a3,
                                         uint32_t b0, uint32_t b1) {
    asm volatile("mma.sync.aligned.m16n8k16.row.col.f32.f16.f16.f32 "
                 "{%0,%1,%2,%3}, {%4,%5,%6,%7}, {%8,%9}, {%0,%1,%2,%3};"
                 : "+f"(d[0]), "+f"(d[1]), "+f"(d[2]), "+f"(d[3])
                 : "r"(a0), "r"(a1), "r"(a2), "r"(a3), "r"(b0), "r"(b1));
}

__device__ __forceinline__ int detect_is64_block(const int* ei32) {
    __shared__ int s_is64;
    if (threadIdx.x == 0) {
        int az = 1;
#pragma unroll
        for (int t = 0; t < 8; t++) az &= (ei32[2 * t + 1] == 0);
        s_is64 = az;
    }
    __syncthreads();
    return s_is64;
}

// ---------------- CSR build (4 edges per thread) ----------------
__global__ void hist_kernel(const void* __restrict__ ei, int* __restrict__ cnt,
                            const float* __restrict__ x, __half* __restrict__ xh,
                            int nquads, int E) {
    const int is64 = detect_is64_block((const int*)ei);
    const int gid = blockIdx.x * blockDim.x + threadIdx.x;
    const int stride = gridDim.x * blockDim.x;
    for (int i = gid; i < nquads; i += stride) {
        float4 v = reinterpret_cast<const float4*>(x)[i];
        st4h(xh + (size_t)i * 4, v.x, v.y, v.z, v.w);
    }
    const int e0 = gid * 4;
    if (e0 >= E) return;
    if (e0 + 3 < E) {
        int d0, d1, d2, d3;
        if (is64) {
            const longlong2* p = (const longlong2*)((const long long*)ei + E + e0);
            longlong2 a = p[0], b = p[1];
            d0 = (int)a.x; d1 = (int)a.y; d2 = (int)b.x; d3 = (int)b.y;
        } else {
            int4 a = *(const int4*)((const int*)ei + E + e0);
            d0 = a.x; d1 = a.y; d2 = a.z; d3 = a.w;
        }
        atomicAdd(&cnt[d0], 1);
        atomicAdd(&cnt[d1], 1);
        atomicAdd(&cnt[d2], 1);
        atomicAdd(&cnt[d3], 1);
    } else {
        for (int e = e0; e < E; e++) {
            int d = is64 ? (int)((const long long*)ei)[(long long)E + e]
                         : ((const int*)ei)[(long long)E + e];
            atomicAdd(&cnt[d], 1);
        }
    }
}

__global__ void scan_kernel(const int* __restrict__ cnt, int* __restrict__ ptr,
                            int* __restrict__ cur, unsigned long long* __restrict__ flag,
                            int N, int E) {
    __shared__ int ssum[256];
    const int tid = threadIdx.x;
    const int b = blockIdx.x;
    const int base = b * 1024 + tid * 4;

    int v0 = (base + 0 < N) ? cnt[base + 0] : 0;
    int v1 = (base + 1 < N) ? cnt[base + 1] : 0;
    int v2 = (base + 2 < N) ? cnt[base + 2] : 0;
    int v3 = (base + 3 < N) ? cnt[base + 3] : 0;
    int s = v0 + v1 + v2 + v3;
    ssum[tid] = s;
    __syncthreads();
    for (int st = 1; st < 256; st <<= 1) {
        int t = (tid >= st) ? ssum[tid - st] : 0;
        __syncthreads();
        ssum[tid] += t;
        __syncthreads();
    }
    const int my_incl = ssum[tid];
    const int total = ssum[255];

    if (tid == 0)
        atomicExch(&flag[b], (((unsigned long long)(unsigned)total) << 1) | 1ull);

    int agg = 0;
    if (tid < b) {
        unsigned long long f;
        do { f = atomicAdd(&flag[tid], 0ull); } while (!(f & 1ull));
        agg = (int)(f >> 1);
    }
    __syncthreads();
    ssum[tid] = agg;
    __syncthreads();
    for (int st = 128; st; st >>= 1) {
        if (tid < st) ssum[tid] += ssum[tid + st];
        __syncthreads();
    }
    const int prev = ssum[0];

    int off = prev + my_incl - s;
    if (base + 0 < N) { ptr[base + 0] = off; cur[base + 0] = off; }  off += v0;
    if (base + 1 < N) { ptr[base + 1] = off; cur[base + 1] = off; }  off += v1;
    if (base + 2 < N) { ptr[base + 2] = off; cur[base + 2] = off; }  off += v2;
    if (base + 3 < N) { ptr[base + 3] = off; cur[base + 3] = off; }
    if (b == 0 && tid == 0) ptr[N] = E;
}

__global__ void scatter_kernel(const void* __restrict__ ei, int* __restrict__ cur,
                               int* __restrict__ csr, int* __restrict__ cnt,
                               unsigned long long* __restrict__ flag, int N, int E) {
    const int is64 = detect_is64_block((const int*)ei);
    const int gid = blockIdx.x * blockDim.x + threadIdx.x;
    if (gid < 128) flag[gid] = 0ull;
    if (gid < N) cnt[gid] = 0;
    const int e0 = gid * 4;
    if (e0 >= E) return;
    if (e0 + 3 < E) {
        int s0, s1, s2, s3, d0, d1, d2, d3;
        if (is64) {
            const longlong2* ps = (const longlong2*)((const long long*)ei + e0);
            const longlong2* pd = (const longlong2*)((const long long*)ei + E + e0);
            longlong2 a = ps[0], b = ps[1], c = pd[0], d = pd[1];
            s0 = (int)a.x; s1 = (int)a.y; s2 = (int)b.x; s3 = (int)b.y;
            d0 = (int)c.x; d1 = (int)c.y; d2 = (int)d.x; d3 = (int)d.y;
        } else {
            int4 a = *(const int4*)((const int*)ei + e0);
            int4 c = *(const int4*)((const int*)ei + E + e0);
            s0 = a.x; s1 = a.y; s2 = a.z; s3 = a.w;
            d0 = c.x; d1 = c.y; d2 = c.z; d3 = c.w;
        }
        csr[atomicAdd(&cur[d0], 1)] = s0;
        csr[atomicAdd(&cur[d1], 1)] = s1;
        csr[atomicAdd(&cur[d2], 1)] = s2;
        csr[atomicAdd(&cur[d3], 1)] = s3;
    } else {
        for (int e = e0; e < E; e++) {
            int s, d;
            if (is64) {
                s = (int)((const long long*)ei)[e];
                d = (int)((const long long*)ei)[(long long)E + e];
            } else {
                s = ((const int*)ei)[e];
                d = ((const int*)ei)[(long long)E + e];
            }
            csr[atomicAdd(&cur[d], 1)] = s;
        }
    }
}

// ---------------- gather + mean (full fp16 accumulation) ----------------
// 16 lanes per node; lane q owns feature quad [4q,4q+4) = 8B fp16.
// Main loop: full 16-edge batches, 4 ops/edge. Tail: one branch-free
// predicated batch (invalid slots read the zero row).
__global__ void __launch_bounds__(256) gather_mean(
    const __half* __restrict__ feat, const int* __restrict__ ptr,
    const int* __restrict__ csr, __half* __restrict__ mean, int N)
{
    const int gid = blockIdx.x * 256 + threadIdx.x;
    const int n = gid >> 4;
    const int q = gid & 15;
    const unsigned gmask = ((threadIdx.x & 31) < 16) ? 0x0000FFFFu : 0xFFFF0000u;

    int rs = 0, re = 0;
    if (n < N) { rs = ptr[n]; re = ptr[n + 1]; }

    __half2 c0 = __floats2half2_rn(0.f, 0.f), c1 = c0, c2 = c0, c3 = c0;
    const __half* fq = feat + q * 4;
    const __half* zq = g_zero + q * 4;

    int b = rs;
    // ---- full batches: 1 shfl + 1 LDG + 2 HADD2 per edge ----
    for (; b + 16 <= re; b += 16) {
        int idx = csr[b + q];
#pragma unroll
        for (int h = 0; h < 16; h += 8) {
            int s0 = __shfl_sync(gmask, idx, h + 0, 16);
            int s1 = __shfl_sync(gmask, idx, h + 1, 16);
            int s2 = __shfl_sync(gmask, idx, h + 2, 16);
            int s3 = __shfl_sync(gmask, idx, h + 3, 16);
            int s4 = __shfl_sync(gmask, idx, h + 4, 16);
            int s5 = __shfl_sync(gmask, idx, h + 5, 16);
            int s6 = __shfl_sync(gmask, idx, h + 6, 16);
            int s7 = __shfl_sync(gmask, idx, h + 7, 16);
            uint2 v0 = *(const uint2*)(fq + (size_t)s0 * D);
            uint2 v1 = *(const uint2*)(fq + (size_t)s1 * D);
            uint2 v2 = *(const uint2*)(fq + (size_t)s2 * D);
            uint2 v3 = *(const uint2*)(fq + (size_t)s3 * D);
            uint2 v4 = *(const uint2*)(fq + (size_t)s4 * D);
            uint2 v5 = *(const uint2*)(fq + (size_t)s5 * D);
            uint2 v6 = *(const uint2*)(fq + (size_t)s6 * D);
            uint2 v7 = *(const uint2*)(fq + (size_t)s7 * D);
            c0 = __hadd2(c0, u2h2(v0.x)); c1 = __hadd2(c1, u2h2(v0.y));
            c2 = __hadd2(c2, u2h2(v1.x)); c3 = __hadd2(c3, u2h2(v1.y));
            c0 = __hadd2(c0, u2h2(v2.x)); c1 = __hadd2(c1, u2h2(v2.y));
            c2 = __hadd2(c2, u2h2(v3.x)); c3 = __hadd2(c3, u2h2(v3.y));
            c0 = __hadd2(c0, u2h2(v4.x)); c1 = __hadd2(c1, u2h2(v4.y));
            c2 = __hadd2(c2, u2h2(v5.x)); c3 = __hadd2(c3, u2h2(v5.y));
            c0 = __hadd2(c0, u2h2(v6.x)); c1 = __hadd2(c1, u2h2(v6.y));
            c2 = __hadd2(c2, u2h2(v7.x)); c3 = __hadd2(c3, u2h2(v7.y));
        }
    }
    // ---- tail: one predicated 16-slot batch, invalid -> zero row ----
    if (b < re) {
        const int cnt = re - b;
        int idx = csr[(b + q < re) ? b + q : rs];
#pragma unroll
        for (int h = 0; h < 16; h += 8) {
            int s0 = __shfl_sync(gmask, idx, h + 0, 16);
            int s1 = __shfl_sync(gmask, idx, h + 1, 16);
            int s2 = __shfl_sync(gmask, idx, h + 2, 16);
            int s3 = __shfl_sync(gmask, idx, h + 3, 16);
            int s4 = __shfl_sync(gmask, idx, h + 4, 16);
            int s5 = __shfl_sync(gmask, idx, h + 5, 16);
            int s6 = __shfl_sync(gmask, idx, h + 6, 16);
            int s7 = __shfl_sync(gmask, idx, h + 7, 16);
            const __half* p0 = (h + 0 < cnt) ? fq + (size_t)s0 * D : zq;
            const __half* p1 = (h + 1 < cnt) ? fq + (size_t)s1 * D : zq;
            const __half* p2 = (h + 2 < cnt) ? fq + (size_t)s2 * D : zq;
            const __half* p3 = (h + 3 < cnt) ? fq + (size_t)s3 * D : zq;
            const __half* p4 = (h + 4 < cnt) ? fq + (size_t)s4 * D : zq;
            const __half* p5 = (h + 5 < cnt) ? fq + (size_t)s5 * D : zq;
            const __half* p6 = (h + 6 < cnt) ? fq + (size_t)s6 * D : zq;
            const __half* p7 = (h + 7 < cnt) ? fq + (size_t)s7 * D : zq;
            uint2 v0 = *(const uint2*)p0;
            uint2 v1 = *(const uint2*)p1;
            uint2 v2 = *(const uint2*)p2;
            uint2 v3 = *(const uint2*)p3;
            uint2 v4 = *(const uint2*)p4;
            uint2 v5 = *(const uint2*)p5;
            uint2 v6 = *(const uint2*)p6;
            uint2 v7 = *(const uint2*)p7;
            c0 = __hadd2(c0, u2h2(v0.x)); c1 = __hadd2(c1, u2h2(v0.y));
            c2 = __hadd2(c2, u2h2(v1.x)); c3 = __hadd2(c3, u2h2(v1.y));
            c0 = __hadd2(c0, u2h2(v2.x)); c1 = __hadd2(c1, u2h2(v2.y));
            c2 = __hadd2(c2, u2h2(v3.x)); c3 = __hadd2(c3, u2h2(v3.y));
            c0 = __hadd2(c0, u2h2(v4.x)); c1 = __hadd2(c1, u2h2(v4.y));
            c2 = __hadd2(c2, u2h2(v5.x)); c3 = __hadd2(c3, u2h2(v5.y));
            c0 = __hadd2(c0, u2h2(v6.x)); c1 = __hadd2(c1, u2h2(v6.y));
            c2 = __hadd2(c2, u2h2(v7.x)); c3 = __hadd2(c3, u2h2(v7.y));
        }
    }

    if (n < N) {
        float2 f0 = __half22float2(c0);
        float2 f2 = __half22float2(c2);
        float2 f1 = __half22float2(c1);
        float2 f3 = __half22float2(c3);
        const float invd = 1.0f / fmaxf((float)(re - rs), 1.0f);
        st4h(mean + (size_t)n * D + q * 4,
             (f0.x + f2.x) * invd, (f0.y + f2.y) * invd,
             (f1.x + f3.x) * invd, (f1.y + f3.y) * invd);
    }
}

// ---------------- HMMA SAGE transform (unchanged from R9) ----------------
template<bool HEAD>
__global__ void __launch_bounds__(256) hmma_transform(
    const __half* __restrict__ mean, const __half* __restrict__ xsrc,
    const float* __restrict__ Wl, const float* __restrict__ bl,
    const float* __restrict__ Wr, const float* __restrict__ Wo,
    const float* __restrict__ bo, void* __restrict__ outp, int N)
{
    extern __shared__ char smem[];
    char* SA = smem;                               // 32768 B
    char* SB = smem + 32768;                       // 16384 B
    float* bls = (float*)(smem + 49152);
    float* bos = (float*)(smem + 49408);

    const int tid = threadIdx.x;
    const int w = tid >> 5, lane = tid & 31;
    const int base = blockIdx.x * 128;

    if (tid < 64) { bls[tid] = bl[tid]; if (HEAD) bos[tid] = bo[tid]; }

    for (int i = tid; i < 2048; i += 256) {
        const int row = i >> 4, c = i & 15;
        const int n = base + row;
        uint4 val = make_uint4(0u, 0u, 0u, 0u);
        if (n < N) {
            val = (c < 8) ? *(const uint4*)(mean + (size_t)n * D + c * 8)
                          : *(const uint4*)(xsrc + (size_t)n * D + (c - 8) * 8);
        }
        *(uint4*)(SA + row * 256 + ((c ^ (row & 7)) << 4)) = val;
    }
    for (int i = tid; i < 1024; i += 256) {
        const int row = i >> 4, c = i & 15;
        const float* src = (c < 8) ? (Wl + row * D + c * 8)
                                   : (Wr + row * D + (c - 8) * 8);
        float4 f0 = *(const float4*)src;
        float4 f1 = *(const float4*)(src + 4);
        *(uint4*)(SB + row * 256 + ((c ^ (row & 7)) << 4)) = pack8h(f0, f1);
    }
    __syncthreads();

    float acc[8][4];
#pragma unroll
    for (int t = 0; t < 8; t++)
        acc[t][0] = acc[t][1] = acc[t][2] = acc[t][3] = 0.f;

    const int arow = 16 * w + (lane & 15);
    const int ac = lane >> 4;
    const int bn = (lane & 7) + ((lane >> 4) << 3);
    const int bc = (lane >> 3) & 1;

#pragma unroll
    for (int t = 0; t < 8; t++) {
        uint32_t a0, a1, a2, a3;
        uint32_t aaddr = smem_u32(SA + arow * 256 + (((2 * t + ac) ^ (arow & 7)) << 4));
        LDSM_X4(a0, a1, a2, a3, aaddr);
#pragma unroll
        for (int p = 0; p < 4; p++) {
            const int nn = bn + 16 * p;
            uint32_t baddr = smem_u32(SB + nn * 256 + (((2 * t + bc) ^ (nn & 7)) << 4));
            uint32_t b0, b1, b2, b3;
            LDSM_X4(b0, b1, b2, b3, baddr);
            mma16816(acc[2 * p + 0], a0, a1, a2, a3, b0, b1);
            mma16816(acc[2 * p + 1], a0, a1, a2, a3, b2, b3);
        }
    }
    __syncthreads();

    const int r0 = 16 * w + (lane >> 2);
    const int r1 = r0 + 8;
    const int cb = 2 * (lane & 3);
#pragma unroll
    for (int t = 0; t < 8; t++) {
        const int c = 8 * t + cb;
        acc[t][0] = fmaxf(acc[t][0] + bls[c],     0.f);
        acc[t][1] = fmaxf(acc[t][1] + bls[c + 1], 0.f);
        acc[t][2] = fmaxf(acc[t][2] + bls[c],     0.f);
        acc[t][3] = fmaxf(acc[t][3] + bls[c + 1], 0.f);
    }

    if (!HEAD) {
#pragma unroll
        for (int t = 0; t < 8; t++) {
            const int c = 8 * t + cb;
            *(__half2*)(SA + r0 * 144 + c * 2) = __floats2half2_rn(acc[t][0], acc[t][1]);
            *(__half2*)(SA + r1 * 144 + c * 2) = __floats2half2_rn(acc[t][2], acc[t][3]);
        }
        __syncthreads();
        for (int i = tid; i < 1024; i += 256) {
            const int row = i >> 3, c8 = i & 7;
            if (base + row < N)
                *(uint4*)((__half*)outp + (size_t)(base + row) * D + c8 * 8) =
                    *(uint4*)(SA + row * 144 + c8 * 16);
        }
    } else {
#pragma unroll
        for (int t = 0; t < 8; t++) {
            *(__half2*)(SA + r0 * 128 + ((t ^ (r0 & 7)) << 4) + cb * 2) =
                __floats2half2_rn(acc[t][0], acc[t][1]);
            *(__half2*)(SA + r1 * 128 + ((t ^ (r1 & 7)) << 4) + cb * 2) =
                __floats2half2_rn(acc[t][2], acc[t][3]);
        }
        for (int i = tid; i < 512; i += 256) {
            const int row = i >> 3, c = i & 7;
            float4 f0 = *(const float4*)(Wo + row * D + c * 8);
            float4 f1 = *(const float4*)(Wo + row * D + c * 8 + 4);
            *(uint4*)(SB + row * 128 + ((c ^ (row & 7)) << 4)) = pack8h(f0, f1);
        }
        __syncthreads();

        float ac2[8][4];
#pragma unroll
        for (int t = 0; t < 8; t++)
            ac2[t][0] = ac2[t][1] = ac2[t][2] = ac2[t][3] = 0.f;
#pragma unroll
        for (int t = 0; t < 4; t++) {
            uint32_t a0, a1, a2, a3;
            uint32_t aaddr = smem_u32(SA + arow * 128 + (((2 * t + ac) ^ (arow & 7)) << 4));
            LDSM_X4(a0, a1, a2, a3, aaddr);
#pragma unroll
            for (int p = 0; p < 4; p++) {
                const int nn = bn + 16 * p;
                uint32_t baddr = smem_u32(SB + nn * 128 + (((2 * t + bc) ^ (nn & 7)) << 4));
                uint32_t b0, b1, b2, b3;
                LDSM_X4(b0, b1, b2, b3, baddr);
                mma16816(ac2[2 * p + 0], a0, a1, a2, a3, b0, b1);
                mma16816(ac2[2 * p + 1], a0, a1, a2, a3, b2, b3);
            }
        }
        __syncthreads();

#pragma unroll
        for (int t = 0; t < 8; t++) {
            const int c = 8 * t + cb;
            *(float2*)(smem + r0 * 264 + c * 4) =
                make_float2(ac2[t][0] + bos[c], ac2[t][1] + bos[c + 1]);
            *(float2*)(smem + r1 * 264 + c * 4) =
                make_float2(ac2[t][2] + bos[c], ac2[t][3] + bos[c + 1]);
        }
        __syncthreads();

        if (tid < 128) {
            const float* lr = (const float*)(smem + tid * 264);
            float mx = -1e30f;
#pragma unroll
            for (int c = 0; c < 64; c++) mx = fmaxf(mx, lr[c]);
            float sm = 0.f;
#pragma unroll
            for (int c = 0; c < 64; c++) sm += expf(lr[c] - mx);
            const float lse = mx + logf(sm);
            const int n = base + tid;
            if (n < N) {
                float* op = (float*)outp + (size_t)n * D;
#pragma unroll
                for (int c = 0; c < 64; c += 4) {
                    float4 r = make_float4(lr[c] - lse, lr[c + 1] - lse,
                                           lr[c + 2] - lse, lr[c + 3] - lse);
                    *(float4*)(op + c) = r;
                }
            }
        }
    }
}

// ---------------------------------------------------------------------------
extern "C" void kernel_launch(void* const* d_in, const int* in_sizes, int n_in,
                              void* d_out, int out_size) {
    const float* x    = (const float*)d_in[0];
    const void*  ei   = d_in[1];
    const float* W1l  = (const float*)d_in[2];
    const float* b1l  = (const float*)d_in[3];
    const float* W1r  = (const float*)d_in[4];
    const float* W2l  = (const float*)d_in[5];
    const float* b2l  = (const float*)d_in[6];
    const float* W2r  = (const float*)d_in[7];
    const float* Wout = (const float*)d_in[8];
    const float* bout = (const float*)d_in[9];

    const int N = in_sizes[0] / D;
    const int E = in_sizes[1] / 2;

    int*   cnt;  cudaGetSymbolAddress((void**)&cnt,  g_cnt);
    int*   ptr;  cudaGetSymbolAddress((void**)&ptr,  g_ptr);
    int*   cur;  cudaGetSymbolAddress((void**)&cur,  g_cur);
    unsigned long long* flag; cudaGetSymbolAddress((void**)&flag, g_flag);
    int*   csr;  cudaGetSymbolAddress((void**)&csr,  g_csr);
    __half* mean; cudaGetSymbolAddress((void**)&mean, g_mean);
    __half* xh;  cudaGetSymbolAddress((void**)&xh,   g_xh);
    __half* h1;  cudaGetSymbolAddress((void**)&h1,   g_h1);

    const int SMEM_MMA = 49152 + 512;

    cudaStreamCaptureStatus cs = cudaStreamCaptureStatusNone;
    cudaStreamIsCapturing(0, &cs);
    if (cs == cudaStreamCaptureStatusNone) {
        cudaFuncSetAttribute(hmma_transform<false>,
                             cudaFuncAttributeMaxDynamicSharedMemorySize, SMEM_MMA);
        cudaFuncSetAttribute(hmma_transform<true>,
                             cudaFuncAttributeMaxDynamicSharedMemorySize, SMEM_MMA);
    }

    const int nb = (N + 1023) / 1024;
    const int e4blocks = ((E + 3) / 4 + 255) / 256;   // 4 edges/thread
    const int gblocks = (N * 16 + 255) / 256;
    const int mblocks = (N + 127) / 128;

    // CSR build: [0] hist + x->fp16, [1] scan, [2] scatter(+state reset)
    hist_kernel<<<e4blocks, 256>>>(ei, cnt, x, xh, N * D / 4, E);
    scan_kernel<<<nb, 256>>>(cnt, ptr, cur, flag, N, E);
    scatter_kernel<<<e4blocks, 256>>>(ei, cur, csr, cnt, flag, N, E);

    // Layer 1: [3] gather (profiled), [4] HMMA transform -> fp16 h1
    gather_mean<<<gblocks, 256>>>(xh, ptr, csr, mean, N);
    hmma_transform<false><<<mblocks, 256, SMEM_MMA>>>(
        mean, xh, W1l, b1l, W1r, nullptr, nullptr, h1, N);
    // Layer 2 + head: [5] gather, [6] HMMA transform + head + log_softmax
    gather_mean<<<gblocks, 256>>>(h1, ptr, csr, mean, N);
    hmma_transform<true><<<mblocks, 256, SMEM_MMA>>>(
        mean, h1, W2l, b2l, W2r, Wout, bout, (float*)d_out, N);
}